// round 1
// baseline (speedup 1.0000x reference)
#include <cuda_runtime.h>
#include <math.h>

#define B_   4
#define T_   2048
#define DIMN 1024
#define H_   16
#define HD   64
#define MROWS (B_*T_)          // 8192

// ---------------- scratch (device globals: allocation-free) ----------------
__device__ float g_q[MROWS*DIMN];
__device__ float g_k[MROWS*DIMN];
__device__ float g_v[MROWS*DIMN];
__device__ float g_o[MROWS*DIMN];
__device__ float g_cos[T_*32];
__device__ float g_sin[T_*32];

// ---------------- RoPE tables (double precision to match numpy fp32) -------
__global__ void rope_tables_kernel() {
    int idx = blockIdx.x * blockDim.x + threadIdx.x;
    if (idx >= T_*32) return;
    int t = idx >> 5;
    int j = idx & 31;
    double inv = pow(10000.0, -(double)(2*j) / 64.0);
    float invf = (float)inv;                 // numpy computes inv_freq in fp32
    float freq = (float)t * invf;            // fp32 product like np.outer
    g_cos[idx] = (float)cos((double)freq);
    g_sin[idx] = (float)sin((double)freq);
}

// ---------------- RoPE apply (in place on projected q or k) ----------------
__global__ void rope_apply_kernel(float* __restrict__ buf) {
    int idx = blockIdx.x * blockDim.x + threadIdx.x;   // pair index
    if (idx >= MROWS * 512) return;
    int p = idx & 511;          // pair within row (h*32 + j)
    int m = idx >> 9;           // row
    int t = m & (T_ - 1);       // position
    int j = p & 31;
    float2 x = *(float2*)(buf + (size_t)m * DIMN + p * 2);
    float c = g_cos[t*32 + j];
    float s = g_sin[t*32 + j];
    float2 r;
    r.x = x.x * c - x.y * s;
    r.y = x.x * s + x.y * c;
    *(float2*)(buf + (size_t)m * DIMN + p * 2) = r;
}

// ---------------- GEMM: C[M,1024] = A[M,1024] @ W[1024,1024] + bias --------
#define BM 64
#define BN 64
#define BK 16

__global__ __launch_bounds__(256)
void gemm_bias_kernel(const float* __restrict__ A, const float* __restrict__ W,
                      const float* __restrict__ bias, float* __restrict__ C) {
    __shared__ float As[BK][BM];
    __shared__ float Bs[BK][BN];
    int tid = threadIdx.x;
    int m0 = blockIdx.y * BM;
    int n0 = blockIdx.x * BN;
    int tx = tid & 15;
    int ty = tid >> 4;

    // loader indices
    int ar = tid >> 2;            // 0..63 (A row in tile)
    int ac = (tid & 3) * 4;       // 0,4,8,12 (k offset)
    int br = tid >> 4;            // 0..15 (W k-row in tile)
    int bc = (tid & 15) * 4;      // 0..60 (n offset)

    float acc[4][4];
    #pragma unroll
    for (int i = 0; i < 4; i++)
        #pragma unroll
        for (int j = 0; j < 4; j++) acc[i][j] = 0.f;

    for (int k0 = 0; k0 < 1024; k0 += BK) {
        float4 av = *(const float4*)(A + (size_t)(m0 + ar) * 1024 + k0 + ac);
        float4 bv = *(const float4*)(W + (size_t)(k0 + br) * 1024 + n0 + bc);
        As[ac + 0][ar] = av.x;
        As[ac + 1][ar] = av.y;
        As[ac + 2][ar] = av.z;
        As[ac + 3][ar] = av.w;
        *(float4*)&Bs[br][bc] = bv;
        __syncthreads();
        #pragma unroll
        for (int kk = 0; kk < BK; kk++) {
            float4 a4 = *(float4*)&As[kk][ty * 4];
            float4 b4 = *(float4*)&Bs[kk][tx * 4];
            acc[0][0] += a4.x * b4.x; acc[0][1] += a4.x * b4.y;
            acc[0][2] += a4.x * b4.z; acc[0][3] += a4.x * b4.w;
            acc[1][0] += a4.y * b4.x; acc[1][1] += a4.y * b4.y;
            acc[1][2] += a4.y * b4.z; acc[1][3] += a4.y * b4.w;
            acc[2][0] += a4.z * b4.x; acc[2][1] += a4.z * b4.y;
            acc[2][2] += a4.z * b4.z; acc[2][3] += a4.z * b4.w;
            acc[3][0] += a4.w * b4.x; acc[3][1] += a4.w * b4.y;
            acc[3][2] += a4.w * b4.z; acc[3][3] += a4.w * b4.w;
        }
        __syncthreads();
    }
    #pragma unroll
    for (int i = 0; i < 4; i++) {
        #pragma unroll
        for (int j = 0; j < 4; j++) {
            int col = n0 + tx * 4 + j;
            C[(size_t)(m0 + ty * 4 + i) * 1024 + col] = acc[i][j] + bias[col];
        }
    }
}

// ---------------- Flash attention: thread-per-query-row, fp32 --------------
// grid: (T/128, H, B), block: 128 threads; smem 64 KB
__global__ __launch_bounds__(128, 3)
void attn_kernel(const float* __restrict__ Q, const float* __restrict__ K,
                 const float* __restrict__ V, float* __restrict__ O) {
    extern __shared__ float sm[];
    float* Ks = sm;            // 64*64
    float* Vs = sm + 4096;     // 64*64
    float* Ss = sm + 8192;     // 128*64 (row-private score scratch)

    int tid = threadIdx.x;
    int qt = blockIdx.x, h = blockIdx.y, b = blockIdx.z;
    int q0 = qt * 128;
    int row = q0 + tid;

    const float* qp = Q + ((size_t)(b * T_ + row)) * DIMN + h * HD;
    float qreg[64];
    #pragma unroll
    for (int i = 0; i < 16; i++) {
        float4 v4 = *(const float4*)(qp + 4 * i);
        qreg[4*i+0] = v4.x * 0.125f;
        qreg[4*i+1] = v4.y * 0.125f;
        qreg[4*i+2] = v4.z * 0.125f;
        qreg[4*i+3] = v4.w * 0.125f;
    }
    float oacc[64];
    #pragma unroll
    for (int i = 0; i < 64; i++) oacc[i] = 0.f;
    float mrow = -1e30f, lrow = 0.f;
    float* srow = Ss + tid * 64;

    for (int s0 = 0; s0 <= q0 + 127; s0 += 64) {
        __syncthreads();  // previous tile's Ks/Vs fully consumed
        #pragma unroll
        for (int i = 0; i < 8; i++) {
            int e   = tid + 128 * i;     // float4 index into 64x64 tile
            int srw = e >> 4;
            int dc  = (e & 15) << 2;
            size_t g = ((size_t)(b * T_ + s0 + srw)) * DIMN + h * HD + dc;
            *(float4*)(Ks + srw * 64 + dc) = *(const float4*)(K + g);
            *(float4*)(Vs + srw * 64 + dc) = *(const float4*)(V + g);
        }
        __syncthreads();

        int lim = row - s0;          // valid: s <= lim
        float mt = -1e30f;
        #pragma unroll 2
        for (int s = 0; s < 64; s++) {
            const float4* kr = (const float4*)(Ks + s * 64);
            float a = 0.f;
            #pragma unroll
            for (int d = 0; d < 16; d++) {
                float4 kv = kr[d];
                a += qreg[4*d+0] * kv.x + qreg[4*d+1] * kv.y
                   + qreg[4*d+2] * kv.z + qreg[4*d+3] * kv.w;
            }
            a = (s <= lim) ? a : -1e30f;
            mt = fmaxf(mt, a);
            srow[s] = a;
        }
        float mnew = fmaxf(mrow, mt);
        float corr = __expf(mrow - mnew);
        lrow *= corr;
        #pragma unroll
        for (int i = 0; i < 64; i++) oacc[i] *= corr;

        float psum = 0.f;
        #pragma unroll 4
        for (int s = 0; s < 64; s++) {
            float p = __expf(srow[s] - mnew);
            psum += p;
            srow[s] = p;
        }
        lrow += psum;
        mrow = mnew;

        #pragma unroll 2
        for (int s = 0; s < 64; s++) {
            float p = srow[s];
            const float4* vr = (const float4*)(Vs + s * 64);
            #pragma unroll
            for (int d = 0; d < 16; d++) {
                float4 vv = vr[d];
                oacc[4*d+0] += p * vv.x;
                oacc[4*d+1] += p * vv.y;
                oacc[4*d+2] += p * vv.z;
                oacc[4*d+3] += p * vv.w;
            }
        }
    }

    float inv = 1.f / lrow;
    float* op = O + ((size_t)(b * T_ + row)) * DIMN + h * HD;
    #pragma unroll
    for (int i = 0; i < 16; i++) {
        float4 r;
        r.x = oacc[4*i+0] * inv;
        r.y = oacc[4*i+1] * inv;
        r.z = oacc[4*i+2] * inv;
        r.w = oacc[4*i+3] * inv;
        *(float4*)(op + 4 * i) = r;
    }
}

// ---------------- launch ---------------------------------------------------
extern "C" void kernel_launch(void* const* d_in, const int* in_sizes, int n_in,
                              void* d_out, int out_size) {
    const float* query = (const float*)d_in[0];
    const float* key   = (const float*)d_in[1];
    const float* value = (const float*)d_in[2];
    const float* Wq    = (const float*)d_in[3];
    const float* bq    = (const float*)d_in[4];
    const float* Wk    = (const float*)d_in[5];
    const float* bk    = (const float*)d_in[6];
    const float* Wv    = (const float*)d_in[7];
    const float* bv    = (const float*)d_in[8];
    const float* Wo    = (const float*)d_in[9];
    const float* bo    = (const float*)d_in[10];
    float* out = (float*)d_out;

    float *qb, *kb, *vb, *ob;
    cudaGetSymbolAddress((void**)&qb, g_q);
    cudaGetSymbolAddress((void**)&kb, g_k);
    cudaGetSymbolAddress((void**)&vb, g_v);
    cudaGetSymbolAddress((void**)&ob, g_o);

    static bool attr_set = false;
    if (!attr_set) {
        cudaFuncSetAttribute(attn_kernel,
                             cudaFuncAttributeMaxDynamicSharedMemorySize, 65536);
        attr_set = true;
    }

    // RoPE tables (tiny)
    rope_tables_kernel<<<(T_*32 + 255) / 256, 256>>>();

    // QKV projections
    dim3 ggrid(DIMN / BN, MROWS / BM);
    gemm_bias_kernel<<<ggrid, 256>>>(query, Wq, bq, qb);
    gemm_bias_kernel<<<ggrid, 256>>>(key,   Wk, bk, kb);
    gemm_bias_kernel<<<ggrid, 256>>>(value, Wv, bv, vb);

    // RoPE on q and k
    int npairs = MROWS * 512;
    rope_apply_kernel<<<(npairs + 255) / 256, 256>>>(qb);
    rope_apply_kernel<<<(npairs + 255) / 256, 256>>>(kb);

    // causal flash attention
    dim3 agrid(T_ / 128, H_, B_);
    attn_kernel<<<agrid, 128, 65536>>>(qb, kb, vb, ob);

    // output projection -> d_out
    gemm_bias_kernel<<<ggrid, 256>>>(ob, Wo, bo, out);
}

// round 2
// speedup vs baseline: 1.1148x; 1.1148x over previous
#include <cuda_runtime.h>
#include <math.h>

#define B_   4
#define T_   2048
#define DIMN 1024
#define H_   16
#define HD   64
#define MROWS (B_*T_)          // 8192

typedef unsigned long long u64;

// ---------------- f32x2 packed-math helpers (sm_103a FFMA2 path) -----------
__device__ __forceinline__ u64 pk2(float lo, float hi) {
    u64 r; asm("mov.b64 %0, {%1,%2};" : "=l"(r) : "f"(lo), "f"(hi)); return r;
}
__device__ __forceinline__ u64 fma2(u64 a, u64 b, u64 c) {
    u64 d; asm("fma.rn.f32x2 %0, %1, %2, %3;" : "=l"(d) : "l"(a), "l"(b), "l"(c));
    return d;
}
__device__ __forceinline__ u64 mul2(u64 a, u64 b) {
    u64 d; asm("mul.rn.f32x2 %0, %1, %2;" : "=l"(d) : "l"(a), "l"(b)); return d;
}
__device__ __forceinline__ float2 up2(u64 v) {
    float2 f; asm("mov.b64 {%0,%1}, %2;" : "=f"(f.x), "=f"(f.y) : "l"(v)); return f;
}

// ---------------- scratch (device globals: allocation-free) ----------------
__device__ float g_q[MROWS*DIMN];
__device__ float g_k[MROWS*DIMN];
__device__ float g_v[MROWS*DIMN];
__device__ float g_o[MROWS*DIMN];
__device__ float g_cos[T_*32];
__device__ float g_sin[T_*32];

// ---------------- RoPE tables (double precision to match numpy fp32) -------
__global__ void rope_tables_kernel() {
    int idx = blockIdx.x * blockDim.x + threadIdx.x;
    if (idx >= T_*32) return;
    int t = idx >> 5;
    int j = idx & 31;
    double inv = pow(10000.0, -(double)(2*j) / 64.0);
    float invf = (float)inv;
    float freq = (float)t * invf;
    g_cos[idx] = (float)cos((double)freq);
    g_sin[idx] = (float)sin((double)freq);
}

// ---------------- RoPE apply (in place on projected q or k) ----------------
__global__ void rope_apply_kernel(float* __restrict__ buf) {
    int idx = blockIdx.x * blockDim.x + threadIdx.x;   // pair index
    if (idx >= MROWS * 512) return;
    int p = idx & 511;
    int m = idx >> 9;
    int t = m & (T_ - 1);
    int j = p & 31;
    float2 x = *(float2*)(buf + (size_t)m * DIMN + p * 2);
    float c = g_cos[t*32 + j];
    float s = g_sin[t*32 + j];
    float2 r;
    r.x = x.x * c - x.y * s;
    r.y = x.x * s + x.y * c;
    *(float2*)(buf + (size_t)m * DIMN + p * 2) = r;
}

// ---------------- GEMM: C[M,1024] = A[M,1024] @ W[1024,1024] + bias --------
// 128x128 block tile, BK=16, 256 threads, 8x8 micro-tile via f32x2.
// A tile stored splat-duplicated in smem so FFMA2 splat operand is a plain LDS.
__global__ __launch_bounds__(256)
void gemm_bias_kernel(const float* __restrict__ A, const float* __restrict__ W,
                      const float* __restrict__ bias, float* __restrict__ C) {
    __shared__ float Asd[16][256];   // Asd[k][2m] = Asd[k][2m+1] = A[m][k]  (16KB)
    __shared__ float Bs[16][128];    // Bs[k][n]                              (8KB)

    int tid = threadIdx.x;
    int tx  = tid & 15;              // n-group
    int ty  = tid >> 4;              // m-group
    int m0  = blockIdx.y * 128;
    int nb  = blockIdx.x * 128;

    // A-loader: two float4 per thread per k-step
    int v0 = tid * 2, v1 = tid * 2 + 1;
    int ar0 = v0 >> 2, ak0 = (v0 & 3) * 4;
    int ar1 = v1 >> 2, ak1 = (v1 & 3) * 4;
    // B-loader: two float4 per thread per k-step
    int bk0 = tid >> 5,     bn0 = (tid & 31) * 4;
    int bk1 = 8 + (tid >> 5);

    const float* Ap0 = A + (size_t)(m0 + ar0) * 1024 + ak0;
    const float* Ap1 = A + (size_t)(m0 + ar1) * 1024 + ak1;
    const float* Wp0 = W + (size_t)bk0 * 1024 + nb + bn0;
    const float* Wp1 = W + (size_t)bk1 * 1024 + nb + bn0;

    u64 acc[8][4];
    #pragma unroll
    for (int i = 0; i < 8; i++)
        #pragma unroll
        for (int j = 0; j < 4; j++) acc[i][j] = 0ull;

    // prologue: fetch k0=0
    float4 fa0 = *(const float4*)(Ap0);
    float4 fa1 = *(const float4*)(Ap1);
    float4 fb0 = *(const float4*)(Wp0);
    float4 fb1 = *(const float4*)(Wp1);

    for (int k0 = 0; k0 < 1024; k0 += 16) {
        // store current regs -> smem
        *(float2*)&Asd[ak0+0][2*ar0] = make_float2(fa0.x, fa0.x);
        *(float2*)&Asd[ak0+1][2*ar0] = make_float2(fa0.y, fa0.y);
        *(float2*)&Asd[ak0+2][2*ar0] = make_float2(fa0.z, fa0.z);
        *(float2*)&Asd[ak0+3][2*ar0] = make_float2(fa0.w, fa0.w);
        *(float2*)&Asd[ak1+0][2*ar1] = make_float2(fa1.x, fa1.x);
        *(float2*)&Asd[ak1+1][2*ar1] = make_float2(fa1.y, fa1.y);
        *(float2*)&Asd[ak1+2][2*ar1] = make_float2(fa1.z, fa1.z);
        *(float2*)&Asd[ak1+3][2*ar1] = make_float2(fa1.w, fa1.w);
        *(float4*)&Bs[bk0][bn0] = fb0;
        *(float4*)&Bs[bk1][bn0] = fb1;
        __syncthreads();

        // prefetch next tile (hidden behind compute)
        if (k0 + 16 < 1024) {
            fa0 = *(const float4*)(Ap0 + k0 + 16);
            fa1 = *(const float4*)(Ap1 + k0 + 16);
            fb0 = *(const float4*)(Wp0 + (size_t)(k0 + 16) * 1024);
            fb1 = *(const float4*)(Wp1 + (size_t)(k0 + 16) * 1024);
        }

        #pragma unroll
        for (int kk = 0; kk < 16; kk++) {
            const ulonglong2* ap = (const ulonglong2*)&Asd[kk][ty * 16];
            const ulonglong2* bp0 = (const ulonglong2*)&Bs[kk][tx * 4];
            const ulonglong2* bp1 = (const ulonglong2*)&Bs[kk][64 + tx * 4];
            ulonglong2 a01 = ap[0], a23 = ap[1], a45 = ap[2], a67 = ap[3];
            ulonglong2 bl = *bp0, bh = *bp1;
            u64 as[8] = {a01.x, a01.y, a23.x, a23.y, a45.x, a45.y, a67.x, a67.y};
            u64 bs[4] = {bl.x, bl.y, bh.x, bh.y};
            #pragma unroll
            for (int i = 0; i < 8; i++) {
                #pragma unroll
                for (int j = 0; j < 4; j++)
                    acc[i][j] = fma2(as[i], bs[j], acc[i][j]);
            }
        }
        __syncthreads();
    }

    float4 bia0 = *(const float4*)(bias + nb + tx * 4);
    float4 bia1 = *(const float4*)(bias + nb + 64 + tx * 4);
    #pragma unroll
    for (int i = 0; i < 8; i++) {
        int row = m0 + ty * 8 + i;
        float2 p0 = up2(acc[i][0]);
        float2 p1 = up2(acc[i][1]);
        float2 p2 = up2(acc[i][2]);
        float2 p3 = up2(acc[i][3]);
        float4 o0 = make_float4(p0.x + bia0.x, p0.y + bia0.y, p1.x + bia0.z, p1.y + bia0.w);
        float4 o1 = make_float4(p2.x + bia1.x, p2.y + bia1.y, p3.x + bia1.z, p3.y + bia1.w);
        *(float4*)(C + (size_t)row * 1024 + nb + tx * 4)      = o0;
        *(float4*)(C + (size_t)row * 1024 + nb + 64 + tx * 4) = o1;
    }
}

// ---------------- Flash attention: thread-per-query-row, f32x2 -------------
// grid: (T/128, H, B), block: 128 threads; smem 64 KB
__global__ __launch_bounds__(128, 2)
void attn_kernel(const float* __restrict__ Q, const float* __restrict__ K,
                 const float* __restrict__ V, float* __restrict__ O) {
    extern __shared__ float sm[];
    float* Ks = sm;            // 64*64
    float* Vs = sm + 4096;     // 64*64
    float* Ss = sm + 8192;     // 128*64 (row-private score scratch)

    int tid = threadIdx.x;
    int qt = blockIdx.x, h = blockIdx.y, b = blockIdx.z;
    int q0 = qt * 128;
    int row = q0 + tid;

    const float* qp = Q + ((size_t)(b * T_ + row)) * DIMN + h * HD;
    u64 q2[32];
    #pragma unroll
    for (int i = 0; i < 16; i++) {
        float4 v4 = *(const float4*)(qp + 4 * i);
        q2[2*i]   = pk2(v4.x * 0.125f, v4.y * 0.125f);
        q2[2*i+1] = pk2(v4.z * 0.125f, v4.w * 0.125f);
    }
    u64 oacc[32];
    #pragma unroll
    for (int i = 0; i < 32; i++) oacc[i] = 0ull;
    float mrow = -1e30f, lrow = 0.f;
    float* srow = Ss + tid * 64;

    for (int s0 = 0; s0 <= q0 + 127; s0 += 64) {
        __syncthreads();
        #pragma unroll
        for (int i = 0; i < 8; i++) {
            int e   = tid + 128 * i;
            int srw = e >> 4;
            int dc  = (e & 15) << 2;
            size_t g = ((size_t)(b * T_ + s0 + srw)) * DIMN + h * HD + dc;
            *(float4*)(Ks + srw * 64 + dc) = *(const float4*)(K + g);
            *(float4*)(Vs + srw * 64 + dc) = *(const float4*)(V + g);
        }
        __syncthreads();

        int lim = row - s0;          // valid: s <= lim
        float mt = -1e30f;
        #pragma unroll 2
        for (int s = 0; s < 64; s++) {
            const ulonglong2* kr = (const ulonglong2*)(Ks + s * 64);
            u64 ac0 = 0ull, ac1 = 0ull;
            #pragma unroll
            for (int d = 0; d < 16; d++) {
                ulonglong2 kv = kr[d];
                ac0 = fma2(q2[2*d],   kv.x, ac0);
                ac1 = fma2(q2[2*d+1], kv.y, ac1);
            }
            float2 r0 = up2(ac0);
            float2 r1 = up2(ac1);
            float a = (r0.x + r0.y) + (r1.x + r1.y);
            a = (s <= lim) ? a : -1e30f;
            mt = fmaxf(mt, a);
            srow[s] = a;
        }
        float mnew = fmaxf(mrow, mt);
        float corr = __expf(mrow - mnew);
        lrow *= corr;
        u64 corr2 = pk2(corr, corr);
        #pragma unroll
        for (int i = 0; i < 32; i++) oacc[i] = mul2(oacc[i], corr2);

        float psum = 0.f;
        #pragma unroll 4
        for (int s = 0; s < 64; s++) {
            float p = __expf(srow[s] - mnew);
            psum += p;
            srow[s] = p;
        }
        lrow += psum;
        mrow = mnew;

        #pragma unroll 2
        for (int s = 0; s < 64; s++) {
            u64 p2 = pk2(srow[s], srow[s]);
            const ulonglong2* vr = (const ulonglong2*)(Vs + s * 64);
            #pragma unroll
            for (int d = 0; d < 16; d++) {
                ulonglong2 vv = vr[d];
                oacc[2*d]   = fma2(p2, vv.x, oacc[2*d]);
                oacc[2*d+1] = fma2(p2, vv.y, oacc[2*d+1]);
            }
        }
    }

    float inv = 1.f / lrow;
    float* op = O + ((size_t)(b * T_ + row)) * DIMN + h * HD;
    #pragma unroll
    for (int i = 0; i < 16; i++) {
        float2 e0 = up2(oacc[2*i]);
        float2 e1 = up2(oacc[2*i+1]);
        float4 r = make_float4(e0.x * inv, e0.y * inv, e1.x * inv, e1.y * inv);
        *(float4*)(op + 4 * i) = r;
    }
}

// ---------------- launch ---------------------------------------------------
extern "C" void kernel_launch(void* const* d_in, const int* in_sizes, int n_in,
                              void* d_out, int out_size) {
    const float* query = (const float*)d_in[0];
    const float* key   = (const float*)d_in[1];
    const float* value = (const float*)d_in[2];
    const float* Wq    = (const float*)d_in[3];
    const float* bq    = (const float*)d_in[4];
    const float* Wk    = (const float*)d_in[5];
    const float* bk    = (const float*)d_in[6];
    const float* Wv    = (const float*)d_in[7];
    const float* bv    = (const float*)d_in[8];
    const float* Wo    = (const float*)d_in[9];
    const float* bo    = (const float*)d_in[10];
    float* out = (float*)d_out;

    float *qb, *kb, *vb, *ob;
    cudaGetSymbolAddress((void**)&qb, g_q);
    cudaGetSymbolAddress((void**)&kb, g_k);
    cudaGetSymbolAddress((void**)&vb, g_v);
    cudaGetSymbolAddress((void**)&ob, g_o);

    static bool attr_set = false;
    if (!attr_set) {
        cudaFuncSetAttribute(attn_kernel,
                             cudaFuncAttributeMaxDynamicSharedMemorySize, 65536);
        attr_set = true;
    }

    rope_tables_kernel<<<(T_*32 + 255) / 256, 256>>>();

    dim3 ggrid(DIMN / 128, MROWS / 128);
    gemm_bias_kernel<<<ggrid, 256>>>(query, Wq, bq, qb);
    gemm_bias_kernel<<<ggrid, 256>>>(key,   Wk, bk, kb);
    gemm_bias_kernel<<<ggrid, 256>>>(value, Wv, bv, vb);

    int npairs = MROWS * 512;
    rope_apply_kernel<<<(npairs + 255) / 256, 256>>>(qb);
    rope_apply_kernel<<<(npairs + 255) / 256, 256>>>(kb);

    dim3 agrid(T_ / 128, H_, B_);
    attn_kernel<<<agrid, 128, 65536>>>(qb, kb, vb, ob);

    gemm_bias_kernel<<<ggrid, 256>>>(ob, Wo, bo, out);
}

// round 4
// speedup vs baseline: 1.5162x; 1.3601x over previous
#include <cuda_runtime.h>
#include <cuda_bf16.h>
#include <math.h>
#include <stdint.h>

#define B_   4
#define T_   2048
#define DIMN 1024
#define H_   16
#define HD   64
#define MROWS (B_*T_)          // 8192

typedef unsigned long long u64;

// ---------------- f32x2 packed-math helpers (attention) --------------------
__device__ __forceinline__ u64 pk2(float lo, float hi) {
    u64 r; asm("mov.b64 %0, {%1,%2};" : "=l"(r) : "f"(lo), "f"(hi)); return r;
}
__device__ __forceinline__ u64 fma2(u64 a, u64 b, u64 c) {
    u64 d; asm("fma.rn.f32x2 %0, %1, %2, %3;" : "=l"(d) : "l"(a), "l"(b), "l"(c));
    return d;
}
__device__ __forceinline__ u64 mul2(u64 a, u64 b) {
    u64 d; asm("mul.rn.f32x2 %0, %1, %2;" : "=l"(d) : "l"(a), "l"(b)); return d;
}
__device__ __forceinline__ float2 up2(u64 v) {
    float2 f; asm("mov.b64 {%0,%1}, %2;" : "=f"(f.x), "=f"(f.y) : "l"(v)); return f;
}

// ---------------- smem / mma helpers ----------------------------------------
__device__ __forceinline__ uint32_t smem_u32(const void* p) {
    uint32_t a;
    asm("{ .reg .u64 t; cvta.to.shared.u64 t, %1; cvt.u32.u64 %0, t; }"
        : "=r"(a) : "l"(p));
    return a;
}
__device__ __forceinline__ void cp16(uint32_t dst, const void* src) {
    asm volatile("cp.async.cg.shared.global [%0], [%1], 16;"
                 :: "r"(dst), "l"(src) : "memory");
}
#define CP_COMMIT() asm volatile("cp.async.commit_group;" ::: "memory")
#define CP_WAIT(n)  asm volatile("cp.async.wait_group %0;" :: "n"(n) : "memory")

__device__ __forceinline__ void ldsm4(uint32_t* r, uint32_t addr) {
    asm volatile("ldmatrix.sync.aligned.m8n8.x4.shared.b16 {%0,%1,%2,%3}, [%4];"
                 : "=r"(r[0]), "=r"(r[1]), "=r"(r[2]), "=r"(r[3]) : "r"(addr));
}
__device__ __forceinline__ void mma_bf16(float* c, const uint32_t* a,
                                         uint32_t b0, uint32_t b1) {
    asm volatile(
        "mma.sync.aligned.m16n8k16.row.col.f32.bf16.bf16.f32 "
        "{%0,%1,%2,%3}, {%4,%5,%6,%7}, {%8,%9}, {%0,%1,%2,%3};"
        : "+f"(c[0]), "+f"(c[1]), "+f"(c[2]), "+f"(c[3])
        : "r"(a[0]), "r"(a[1]), "r"(a[2]), "r"(a[3]), "r"(b0), "r"(b1));
}

// ---------------- scratch (device globals) ----------------------------------
__device__ float g_q[MROWS*DIMN];
__device__ float g_k[MROWS*DIMN];
__device__ float g_v[MROWS*DIMN];
__device__ float g_o[MROWS*DIMN];
__device__ float g_cos[T_*32];
__device__ float g_sin[T_*32];
__device__ __nv_bfloat16 g_ahi[MROWS*DIMN];
__device__ __nv_bfloat16 g_alo[MROWS*DIMN];
__device__ __nv_bfloat16 g_whT[DIMN*DIMN];
__device__ __nv_bfloat16 g_wlT[DIMN*DIMN];

// ---------------- RoPE tables -----------------------------------------------
__global__ void rope_tables_kernel() {
    int idx = blockIdx.x * blockDim.x + threadIdx.x;
    if (idx >= T_*32) return;
    int t = idx >> 5;
    int j = idx & 31;
    double inv = pow(10000.0, -(double)(2*j) / 64.0);
    float invf = (float)inv;
    float freq = (float)t * invf;
    g_cos[idx] = (float)cos((double)freq);
    g_sin[idx] = (float)sin((double)freq);
}

// ---------------- RoPE apply -------------------------------------------------
__global__ void rope_apply_kernel(float* __restrict__ buf) {
    int idx = blockIdx.x * blockDim.x + threadIdx.x;
    if (idx >= MROWS * 512) return;
    int p = idx & 511;
    int m = idx >> 9;
    int t = m & (T_ - 1);
    int j = p & 31;
    float2 x = *(float2*)(buf + (size_t)m * DIMN + p * 2);
    float c = g_cos[t*32 + j];
    float s = g_sin[t*32 + j];
    float2 r;
    r.x = x.x * c - x.y * s;
    r.y = x.x * s + x.y * c;
    *(float2*)(buf + (size_t)m * DIMN + p * 2) = r;
}

// ---------------- fp32 -> bf16 hi/lo split (activations) --------------------
__global__ void convert_act_kernel(const float* __restrict__ x,
                                   __nv_bfloat16* __restrict__ hi,
                                   __nv_bfloat16* __restrict__ lo, int n4) {
    int i = blockIdx.x * blockDim.x + threadIdx.x;
    if (i >= n4) return;
    float4 v = ((const float4*)x)[i];
    __nv_bfloat16 h0 = __float2bfloat16(v.x);
    __nv_bfloat16 h1 = __float2bfloat16(v.y);
    __nv_bfloat16 h2 = __float2bfloat16(v.z);
    __nv_bfloat16 h3 = __float2bfloat16(v.w);
    __nv_bfloat162* hp = (__nv_bfloat162*)hi;
    __nv_bfloat162* lp = (__nv_bfloat162*)lo;
    hp[2*i]   = __nv_bfloat162(h0, h1);
    hp[2*i+1] = __nv_bfloat162(h2, h3);
    lp[2*i]   = __nv_bfloat162(__float2bfloat16(v.x - __bfloat162float(h0)),
                               __float2bfloat16(v.y - __bfloat162float(h1)));
    lp[2*i+1] = __nv_bfloat162(__float2bfloat16(v.z - __bfloat162float(h2)),
                               __float2bfloat16(v.w - __bfloat162float(h3)));
}

// ---------------- fp32 W[k][n] -> bf16 hi/lo transposed [n][k] --------------
__global__ void convert_wt_kernel(const float* __restrict__ W,
                                  __nv_bfloat16* __restrict__ hiT,
                                  __nv_bfloat16* __restrict__ loT) {
    __shared__ float t[32][33];
    int tx = threadIdx.x, ty = threadIdx.y;   // 32 x 8
    int n0 = blockIdx.x * 32, k0 = blockIdx.y * 32;
    #pragma unroll
    for (int i = 0; i < 32; i += 8)
        t[ty + i][tx] = W[(size_t)(k0 + ty + i) * DIMN + n0 + tx];
    __syncthreads();
    #pragma unroll
    for (int i = 0; i < 32; i += 8) {
        float x = t[tx][ty + i];
        __nv_bfloat16 h = __float2bfloat16(x);
        size_t o = (size_t)(n0 + ty + i) * DIMN + k0 + tx;
        hiT[o] = h;
        loT[o] = __float2bfloat16(x - __bfloat162float(h));
    }
}

// ---------------- mma.sync bf16-split GEMM -----------------------------------
// C[8192,1024] = A @ W + bias.  128x128 CTA tile, BK=32, 2-stage cp.async.
// smem tile: 128 rows x 32 k bf16, row padded to 40 elems (80B).
// Stage = 4 tiles (Ahi, Alo, Whi, Wlo) = 40960 B; two stages = 81920 B.
#define TILE_B   10240
#define STAGE_B  40960
#define GEMM_SMEM (2*STAGE_B)

__global__ __launch_bounds__(256, 2)
void gemm_tc_kernel(const __nv_bfloat16* __restrict__ a_hi,
                    const __nv_bfloat16* __restrict__ a_lo,
                    const __nv_bfloat16* __restrict__ w_hiT,
                    const __nv_bfloat16* __restrict__ w_loT,
                    const float* __restrict__ bias,
                    float* __restrict__ C) {
    extern __shared__ char smem[];
    uint32_t sb = smem_u32(smem);
    int tid = threadIdx.x, wid = tid >> 5, lane = tid & 31;
    int m0 = blockIdx.y * 128, n0 = blockIdx.x * 128;

    // global sources for the 4 tiles (A rows = m0.., W^T rows = n0..)
    const __nv_bfloat16* srcA_hi = a_hi  + (size_t)m0 * DIMN;
    const __nv_bfloat16* srcA_lo = a_lo  + (size_t)m0 * DIMN;
    const __nv_bfloat16* srcW_hi = w_hiT + (size_t)n0 * DIMN;
    const __nv_bfloat16* srcW_lo = w_loT + (size_t)n0 * DIMN;

    // loader: chunk c -> row c>>2, 16B segment c&3 (2 chunks per thread per tile)
    int r0 = tid >> 2, sg = tid & 3;
    int r1 = r0 + 64;
    uint32_t so0 = (uint32_t)r0 * 80 + sg * 16;
    uint32_t so1 = (uint32_t)r1 * 80 + sg * 16;
    size_t go0 = (size_t)r0 * DIMN + sg * 8;
    size_t go1 = (size_t)r1 * DIMN + sg * 8;

    #define ISSUE(stage, k0)  do {                                            \
        uint32_t _sbs = sb + (stage) * STAGE_B;                               \
        cp16(_sbs + 0*TILE_B + so0, srcA_hi + (k0) + go0);                    \
        cp16(_sbs + 0*TILE_B + so1, srcA_hi + (k0) + go1);                    \
        cp16(_sbs + 1*TILE_B + so0, srcA_lo + (k0) + go0);                    \
        cp16(_sbs + 1*TILE_B + so1, srcA_lo + (k0) + go1);                    \
        cp16(_sbs + 2*TILE_B + so0, srcW_hi + (k0) + go0);                    \
        cp16(_sbs + 2*TILE_B + so1, srcW_hi + (k0) + go1);                    \
        cp16(_sbs + 3*TILE_B + so0, srcW_lo + (k0) + go0);                    \
        cp16(_sbs + 3*TILE_B + so1, srcW_lo + (k0) + go1);                    \
    } while (0)

    // ldmatrix lane addressing
    int m_warp = (wid & 1) * 64;
    int n_warp = (wid >> 1) * 32;
    uint32_t laneA_row = ((lane >> 3) & 1) * 8 + (lane & 7);
    uint32_t laneA_col = (lane >> 4) * 8;
    uint32_t laneB_row = (lane >> 4) * 8 + (lane & 7);
    uint32_t laneB_col = ((lane >> 3) & 1) * 8;
    uint32_t baseA = (uint32_t)(m_warp + laneA_row) * 80 + laneA_col * 2;
    uint32_t baseB = (uint32_t)(n_warp + laneB_row) * 80 + laneB_col * 2;

    float acc[4][4][4];
    #pragma unroll
    for (int i = 0; i < 4; i++)
        #pragma unroll
        for (int j = 0; j < 4; j++)
            #pragma unroll
            for (int q = 0; q < 4; q++) acc[i][j][q] = 0.f;

    ISSUE(0, 0);
    CP_COMMIT();

    for (int kc = 0; kc < 32; kc++) {
        if (kc < 31) {
            ISSUE((kc + 1) & 1, (kc + 1) * 32);
            CP_COMMIT();
            CP_WAIT(1);
        } else {
            CP_WAIT(0);
        }
        __syncthreads();

        uint32_t st = sb + (kc & 1) * STAGE_B;
        #pragma unroll
        for (int ks = 0; ks < 2; ks++) {
            uint32_t A[4][4], BB[2][4], BL[2][4];
            uint32_t aoff = st + baseA + ks * 32;
            uint32_t boff = st + baseB + ks * 32;
            #pragma unroll
            for (int mt = 0; mt < 4; mt++)
                ldsm4(A[mt], aoff + 0*TILE_B + mt * 1280);      // A_hi
            #pragma unroll
            for (int p = 0; p < 2; p++)
                ldsm4(BB[p], boff + 2*TILE_B + p * 1280);       // W_hi
            #pragma unroll
            for (int mt = 0; mt < 4; mt++)
                #pragma unroll
                for (int nt = 0; nt < 4; nt++)
                    mma_bf16(acc[mt][nt], A[mt],
                             BB[nt>>1][(nt&1)*2], BB[nt>>1][(nt&1)*2+1]);
            #pragma unroll
            for (int p = 0; p < 2; p++)
                ldsm4(BL[p], boff + 3*TILE_B + p * 1280);       // W_lo
            #pragma unroll
            for (int mt = 0; mt < 4; mt++)
                #pragma unroll
                for (int nt = 0; nt < 4; nt++)
                    mma_bf16(acc[mt][nt], A[mt],
                             BL[nt>>1][(nt&1)*2], BL[nt>>1][(nt&1)*2+1]);
            #pragma unroll
            for (int mt = 0; mt < 4; mt++)
                ldsm4(A[mt], aoff + 1*TILE_B + mt * 1280);      // A_lo
            #pragma unroll
            for (int mt = 0; mt < 4; mt++)
                #pragma unroll
                for (int nt = 0; nt < 4; nt++)
                    mma_bf16(acc[mt][nt], A[mt],
                             BB[nt>>1][(nt&1)*2], BB[nt>>1][(nt&1)*2+1]);
        }
        __syncthreads();
    }

    // epilogue
    int rb = m0 + m_warp + (lane >> 2);
    int cb = n0 + n_warp + (lane & 3) * 2;
    #pragma unroll
    for (int mt = 0; mt < 4; mt++) {
        #pragma unroll
        for (int nt = 0; nt < 4; nt++) {
            int r = rb + mt * 16;
            int c = cb + nt * 8;
            float2 bv = *(const float2*)(bias + c);
            float2 o0 = make_float2(acc[mt][nt][0] + bv.x, acc[mt][nt][1] + bv.y);
            float2 o1 = make_float2(acc[mt][nt][2] + bv.x, acc[mt][nt][3] + bv.y);
            *(float2*)(C + (size_t)r * DIMN + c)       = o0;
            *(float2*)(C + (size_t)(r + 8) * DIMN + c) = o1;
        }
    }
    #undef ISSUE
}

// ---------------- Flash attention (R2 version, f32x2) ----------------------
__global__ __launch_bounds__(128, 2)
void attn_kernel(const float* __restrict__ Q, const float* __restrict__ K,
                 const float* __restrict__ V, float* __restrict__ O) {
    extern __shared__ float sm[];
    float* Ks = sm;
    float* Vs = sm + 4096;
    float* Ss = sm + 8192;

    int tid = threadIdx.x;
    int qt = blockIdx.x, h = blockIdx.y, b = blockIdx.z;
    int q0 = qt * 128;
    int row = q0 + tid;

    const float* qp = Q + ((size_t)(b * T_ + row)) * DIMN + h * HD;
    u64 q2[32];
    #pragma unroll
    for (int i = 0; i < 16; i++) {
        float4 v4 = *(const float4*)(qp + 4 * i);
        q2[2*i]   = pk2(v4.x * 0.125f, v4.y * 0.125f);
        q2[2*i+1] = pk2(v4.z * 0.125f, v4.w * 0.125f);
    }
    u64 oacc[32];
    #pragma unroll
    for (int i = 0; i < 32; i++) oacc[i] = 0ull;
    float mrow = -1e30f, lrow = 0.f;
    float* srow = Ss + tid * 64;

    for (int s0 = 0; s0 <= q0 + 127; s0 += 64) {
        __syncthreads();
        #pragma unroll
        for (int i = 0; i < 8; i++) {
            int e   = tid + 128 * i;
            int srw = e >> 4;
            int dc  = (e & 15) << 2;
            size_t g = ((size_t)(b * T_ + s0 + srw)) * DIMN + h * HD + dc;
            *(float4*)(Ks + srw * 64 + dc) = *(const float4*)(K + g);
            *(float4*)(Vs + srw * 64 + dc) = *(const float4*)(V + g);
        }
        __syncthreads();

        int lim = row - s0;
        float mt = -1e30f;
        #pragma unroll 2
        for (int s = 0; s < 64; s++) {
            const ulonglong2* kr = (const ulonglong2*)(Ks + s * 64);
            u64 ac0 = 0ull, ac1 = 0ull;
            #pragma unroll
            for (int d = 0; d < 16; d++) {
                ulonglong2 kv = kr[d];
                ac0 = fma2(q2[2*d],   kv.x, ac0);
                ac1 = fma2(q2[2*d+1], kv.y, ac1);
            }
            float2 r0 = up2(ac0);
            float2 r1 = up2(ac1);
            float a = (r0.x + r0.y) + (r1.x + r1.y);
            a = (s <= lim) ? a : -1e30f;
            mt = fmaxf(mt, a);
            srow[s] = a;
        }
        float mnew = fmaxf(mrow, mt);
        float corr = __expf(mrow - mnew);
        lrow *= corr;
        u64 corr2 = pk2(corr, corr);
        #pragma unroll
        for (int i = 0; i < 32; i++) oacc[i] = mul2(oacc[i], corr2);

        float psum = 0.f;
        #pragma unroll 4
        for (int s = 0; s < 64; s++) {
            float p = __expf(srow[s] - mnew);
            psum += p;
            srow[s] = p;
        }
        lrow += psum;
        mrow = mnew;

        #pragma unroll 2
        for (int s = 0; s < 64; s++) {
            u64 p2 = pk2(srow[s], srow[s]);
            const ulonglong2* vr = (const ulonglong2*)(Vs + s * 64);
            #pragma unroll
            for (int d = 0; d < 16; d++) {
                ulonglong2 vv = vr[d];
                oacc[2*d]   = fma2(p2, vv.x, oacc[2*d]);
                oacc[2*d+1] = fma2(p2, vv.y, oacc[2*d+1]);
            }
        }
    }

    float inv = 1.f / lrow;
    float* op = O + ((size_t)(b * T_ + row)) * DIMN + h * HD;
    #pragma unroll
    for (int i = 0; i < 16; i++) {
        float2 e0 = up2(oacc[2*i]);
        float2 e1 = up2(oacc[2*i+1]);
        float4 r = make_float4(e0.x * inv, e0.y * inv, e1.x * inv, e1.y * inv);
        *(float4*)(op + 4 * i) = r;
    }
}

// ---------------- launch ---------------------------------------------------
extern "C" void kernel_launch(void* const* d_in, const int* in_sizes, int n_in,
                              void* d_out, int out_size) {
    const float* query = (const float*)d_in[0];
    const float* key   = (const float*)d_in[1];
    const float* value = (const float*)d_in[2];
    const float* Wq    = (const float*)d_in[3];
    const float* bq    = (const float*)d_in[4];
    const float* Wk    = (const float*)d_in[5];
    const float* bk    = (const float*)d_in[6];
    const float* Wv    = (const float*)d_in[7];
    const float* bv    = (const float*)d_in[8];
    const float* Wo    = (const float*)d_in[9];
    const float* bo    = (const float*)d_in[10];
    float* out = (float*)d_out;

    float *qb, *kb, *vb, *ob;
    __nv_bfloat16 *ahi, *alo, *whT, *wlT;
    cudaGetSymbolAddress((void**)&qb, g_q);
    cudaGetSymbolAddress((void**)&kb, g_k);
    cudaGetSymbolAddress((void**)&vb, g_v);
    cudaGetSymbolAddress((void**)&ob, g_o);
    cudaGetSymbolAddress((void**)&ahi, g_ahi);
    cudaGetSymbolAddress((void**)&alo, g_alo);
    cudaGetSymbolAddress((void**)&whT, g_whT);
    cudaGetSymbolAddress((void**)&wlT, g_wlT);

    static bool attr_set = false;
    if (!attr_set) {
        cudaFuncSetAttribute(attn_kernel,
                             cudaFuncAttributeMaxDynamicSharedMemorySize, 65536);
        cudaFuncSetAttribute(gemm_tc_kernel,
                             cudaFuncAttributeMaxDynamicSharedMemorySize, GEMM_SMEM);
        attr_set = true;
    }

    rope_tables_kernel<<<(T_*32 + 255) / 256, 256>>>();

    dim3 wt_grid(32, 32), wt_blk(32, 8);
    dim3 ggrid(DIMN / 128, MROWS / 128);
    int n4 = MROWS * DIMN / 4;
    int cvt_blocks = (n4 + 255) / 256;

    // Q projection
    convert_wt_kernel<<<wt_grid, wt_blk>>>(Wq, whT, wlT);
    convert_act_kernel<<<cvt_blocks, 256>>>(query, ahi, alo, n4);
    gemm_tc_kernel<<<ggrid, 256, GEMM_SMEM>>>(ahi, alo, whT, wlT, bq, qb);
    // K projection
    convert_wt_kernel<<<wt_grid, wt_blk>>>(Wk, whT, wlT);
    convert_act_kernel<<<cvt_blocks, 256>>>(key, ahi, alo, n4);
    gemm_tc_kernel<<<ggrid, 256, GEMM_SMEM>>>(ahi, alo, whT, wlT, bk, kb);
    // V projection
    convert_wt_kernel<<<wt_grid, wt_blk>>>(Wv, whT, wlT);
    convert_act_kernel<<<cvt_blocks, 256>>>(value, ahi, alo, n4);
    gemm_tc_kernel<<<ggrid, 256, GEMM_SMEM>>>(ahi, alo, whT, wlT, bv, vb);

    // RoPE
    int npairs = MROWS * 512;
    rope_apply_kernel<<<(npairs + 255) / 256, 256>>>(qb);
    rope_apply_kernel<<<(npairs + 255) / 256, 256>>>(kb);

    // attention
    dim3 agrid(T_ / 128, H_, B_);
    attn_kernel<<<agrid, 128, 65536>>>(qb, kb, vb, ob);

    // output projection
    convert_wt_kernel<<<wt_grid, wt_blk>>>(Wo, whT, wlT);
    convert_act_kernel<<<cvt_blocks, 256>>>(ob, ahi, alo, n4);
    gemm_tc_kernel<<<ggrid, 256, GEMM_SMEM>>>(ahi, alo, whT, wlT, bo, out);
}

// round 5
// speedup vs baseline: 4.5452x; 2.9977x over previous
#include <cuda_runtime.h>
#include <cuda_bf16.h>
#include <math.h>
#include <stdint.h>

#define B_   4
#define T_   2048
#define DIMN 1024
#define H_   16
#define HD   64
#define MROWS (B_*T_)          // 8192

// ---------------- smem / mma helpers ----------------------------------------
__device__ __forceinline__ uint32_t smem_u32(const void* p) {
    uint32_t a;
    asm("{ .reg .u64 t; cvta.to.shared.u64 t, %1; cvt.u32.u64 %0, t; }"
        : "=r"(a) : "l"(p));
    return a;
}
__device__ __forceinline__ void cp16(uint32_t dst, const void* src) {
    asm volatile("cp.async.cg.shared.global [%0], [%1], 16;"
                 :: "r"(dst), "l"(src) : "memory");
}
#define CP_COMMIT() asm volatile("cp.async.commit_group;" ::: "memory")
#define CP_WAIT(n)  asm volatile("cp.async.wait_group %0;" :: "n"(n) : "memory")

__device__ __forceinline__ void ldsm4(uint32_t* r, uint32_t addr) {
    asm volatile("ldmatrix.sync.aligned.m8n8.x4.shared.b16 {%0,%1,%2,%3}, [%4];"
                 : "=r"(r[0]), "=r"(r[1]), "=r"(r[2]), "=r"(r[3]) : "r"(addr));
}
__device__ __forceinline__ void ldsm4t(uint32_t* r, uint32_t addr) {
    asm volatile("ldmatrix.sync.aligned.m8n8.x4.trans.shared.b16 {%0,%1,%2,%3}, [%4];"
                 : "=r"(r[0]), "=r"(r[1]), "=r"(r[2]), "=r"(r[3]) : "r"(addr));
}
__device__ __forceinline__ void mma_bf16(float* c, const uint32_t* a,
                                         uint32_t b0, uint32_t b1) {
    asm volatile(
        "mma.sync.aligned.m16n8k16.row.col.f32.bf16.bf16.f32 "
        "{%0,%1,%2,%3}, {%4,%5,%6,%7}, {%8,%9}, {%0,%1,%2,%3};"
        : "+f"(c[0]), "+f"(c[1]), "+f"(c[2]), "+f"(c[3])
        : "r"(a[0]), "r"(a[1]), "r"(a[2]), "r"(a[3]), "r"(b0), "r"(b1));
}
__device__ __forceinline__ uint32_t bits2(__nv_bfloat162 v) {
    return *reinterpret_cast<uint32_t*>(&v);
}

// ---------------- scratch (device globals) ----------------------------------
__device__ float g_q[MROWS*DIMN];
__device__ float g_k[MROWS*DIMN];
__device__ float g_v[MROWS*DIMN];
__device__ float g_o[MROWS*DIMN];
__device__ float g_cos[T_*32];
__device__ float g_sin[T_*32];
__device__ __nv_bfloat16 g_ahi[MROWS*DIMN];
__device__ __nv_bfloat16 g_alo[MROWS*DIMN];
__device__ __nv_bfloat16 g_whT[DIMN*DIMN];
__device__ __nv_bfloat16 g_wlT[DIMN*DIMN];
__device__ __nv_bfloat16 g_qhi[MROWS*DIMN];
__device__ __nv_bfloat16 g_qlo[MROWS*DIMN];
__device__ __nv_bfloat16 g_khi[MROWS*DIMN];
__device__ __nv_bfloat16 g_klo[MROWS*DIMN];
__device__ __nv_bfloat16 g_vhi[MROWS*DIMN];
__device__ __nv_bfloat16 g_vlo[MROWS*DIMN];

// ---------------- RoPE tables -----------------------------------------------
__global__ void rope_tables_kernel() {
    int idx = blockIdx.x * blockDim.x + threadIdx.x;
    if (idx >= T_*32) return;
    int t = idx >> 5;
    int j = idx & 31;
    double inv = pow(10000.0, -(double)(2*j) / 64.0);
    float invf = (float)inv;
    float freq = (float)t * invf;
    g_cos[idx] = (float)cos((double)freq);
    g_sin[idx] = (float)sin((double)freq);
}

// ---------------- RoPE + bf16 hi/lo split (q / k) ---------------------------
__global__ void rope_split_kernel(const float* __restrict__ buf,
                                  __nv_bfloat16* __restrict__ hi,
                                  __nv_bfloat16* __restrict__ lo, float scale) {
    int idx = blockIdx.x * blockDim.x + threadIdx.x;
    if (idx >= MROWS * 512) return;
    int p = idx & 511;
    int m = idx >> 9;
    int t = m & (T_ - 1);
    int j = p & 31;
    float2 x = *(const float2*)(buf + (size_t)m * DIMN + p * 2);
    float c = g_cos[t*32 + j];
    float s = g_sin[t*32 + j];
    float rx = (x.x * c - x.y * s) * scale;
    float ry = (x.x * s + x.y * c) * scale;
    __nv_bfloat16 hx = __float2bfloat16(rx);
    __nv_bfloat16 hy = __float2bfloat16(ry);
    size_t o = (size_t)m * DIMN + p * 2;
    *(__nv_bfloat162*)(hi + o) = __nv_bfloat162(hx, hy);
    *(__nv_bfloat162*)(lo + o) =
        __nv_bfloat162(__float2bfloat16(rx - __bfloat162float(hx)),
                       __float2bfloat16(ry - __bfloat162float(hy)));
}

// ---------------- fp32 -> bf16 hi/lo split -----------------------------------
__global__ void convert_act_kernel(const float* __restrict__ x,
                                   __nv_bfloat16* __restrict__ hi,
                                   __nv_bfloat16* __restrict__ lo, int n4) {
    int i = blockIdx.x * blockDim.x + threadIdx.x;
    if (i >= n4) return;
    float4 v = ((const float4*)x)[i];
    __nv_bfloat16 h0 = __float2bfloat16(v.x);
    __nv_bfloat16 h1 = __float2bfloat16(v.y);
    __nv_bfloat16 h2 = __float2bfloat16(v.z);
    __nv_bfloat16 h3 = __float2bfloat16(v.w);
    __nv_bfloat162* hp = (__nv_bfloat162*)hi;
    __nv_bfloat162* lp = (__nv_bfloat162*)lo;
    hp[2*i]   = __nv_bfloat162(h0, h1);
    hp[2*i+1] = __nv_bfloat162(h2, h3);
    lp[2*i]   = __nv_bfloat162(__float2bfloat16(v.x - __bfloat162float(h0)),
                               __float2bfloat16(v.y - __bfloat162float(h1)));
    lp[2*i+1] = __nv_bfloat162(__float2bfloat16(v.z - __bfloat162float(h2)),
                               __float2bfloat16(v.w - __bfloat162float(h3)));
}

// ---------------- fp32 W[k][n] -> bf16 hi/lo transposed [n][k] --------------
__global__ void convert_wt_kernel(const float* __restrict__ W,
                                  __nv_bfloat16* __restrict__ hiT,
                                  __nv_bfloat16* __restrict__ loT) {
    __shared__ float t[32][33];
    int tx = threadIdx.x, ty = threadIdx.y;   // 32 x 8
    int n0 = blockIdx.x * 32, k0 = blockIdx.y * 32;
    #pragma unroll
    for (int i = 0; i < 32; i += 8)
        t[ty + i][tx] = W[(size_t)(k0 + ty + i) * DIMN + n0 + tx];
    __syncthreads();
    #pragma unroll
    for (int i = 0; i < 32; i += 8) {
        float x = t[tx][ty + i];
        __nv_bfloat16 h = __float2bfloat16(x);
        size_t o = (size_t)(n0 + ty + i) * DIMN + k0 + tx;
        hiT[o] = h;
        loT[o] = __float2bfloat16(x - __bfloat162float(h));
    }
}

// ---------------- mma.sync bf16-split GEMM (unchanged from R4) --------------
#define TILE_B   10240
#define STAGE_B  40960
#define GEMM_SMEM (2*STAGE_B)

__global__ __launch_bounds__(256, 2)
void gemm_tc_kernel(const __nv_bfloat16* __restrict__ a_hi,
                    const __nv_bfloat16* __restrict__ a_lo,
                    const __nv_bfloat16* __restrict__ w_hiT,
                    const __nv_bfloat16* __restrict__ w_loT,
                    const float* __restrict__ bias,
                    float* __restrict__ C) {
    extern __shared__ char smem[];
    uint32_t sb = smem_u32(smem);
    int tid = threadIdx.x, wid = tid >> 5, lane = tid & 31;
    int m0 = blockIdx.y * 128, n0 = blockIdx.x * 128;

    const __nv_bfloat16* srcA_hi = a_hi  + (size_t)m0 * DIMN;
    const __nv_bfloat16* srcA_lo = a_lo  + (size_t)m0 * DIMN;
    const __nv_bfloat16* srcW_hi = w_hiT + (size_t)n0 * DIMN;
    const __nv_bfloat16* srcW_lo = w_loT + (size_t)n0 * DIMN;

    int r0 = tid >> 2, sg = tid & 3;
    int r1 = r0 + 64;
    uint32_t so0 = (uint32_t)r0 * 80 + sg * 16;
    uint32_t so1 = (uint32_t)r1 * 80 + sg * 16;
    size_t go0 = (size_t)r0 * DIMN + sg * 8;
    size_t go1 = (size_t)r1 * DIMN + sg * 8;

    #define ISSUE(stage, k0)  do {                                            \
        uint32_t _sbs = sb + (stage) * STAGE_B;                               \
        cp16(_sbs + 0*TILE_B + so0, srcA_hi + (k0) + go0);                    \
        cp16(_sbs + 0*TILE_B + so1, srcA_hi + (k0) + go1);                    \
        cp16(_sbs + 1*TILE_B + so0, srcA_lo + (k0) + go0);                    \
        cp16(_sbs + 1*TILE_B + so1, srcA_lo + (k0) + go1);                    \
        cp16(_sbs + 2*TILE_B + so0, srcW_hi + (k0) + go0);                    \
        cp16(_sbs + 2*TILE_B + so1, srcW_hi + (k0) + go1);                    \
        cp16(_sbs + 3*TILE_B + so0, srcW_lo + (k0) + go0);                    \
        cp16(_sbs + 3*TILE_B + so1, srcW_lo + (k0) + go1);                    \
    } while (0)

    int m_warp = (wid & 1) * 64;
    int n_warp = (wid >> 1) * 32;
    uint32_t laneA_row = ((lane >> 3) & 1) * 8 + (lane & 7);
    uint32_t laneA_col = (lane >> 4) * 8;
    uint32_t laneB_row = (lane >> 4) * 8 + (lane & 7);
    uint32_t laneB_col = ((lane >> 3) & 1) * 8;
    uint32_t baseA = (uint32_t)(m_warp + laneA_row) * 80 + laneA_col * 2;
    uint32_t baseB = (uint32_t)(n_warp + laneB_row) * 80 + laneB_col * 2;

    float acc[4][4][4];
    #pragma unroll
    for (int i = 0; i < 4; i++)
        #pragma unroll
        for (int j = 0; j < 4; j++)
            #pragma unroll
            for (int q = 0; q < 4; q++) acc[i][j][q] = 0.f;

    ISSUE(0, 0);
    CP_COMMIT();

    for (int kc = 0; kc < 32; kc++) {
        if (kc < 31) {
            ISSUE((kc + 1) & 1, (kc + 1) * 32);
            CP_COMMIT();
            CP_WAIT(1);
        } else {
            CP_WAIT(0);
        }
        __syncthreads();

        uint32_t st = sb + (kc & 1) * STAGE_B;
        #pragma unroll
        for (int ks = 0; ks < 2; ks++) {
            uint32_t A[4][4], BB[2][4], BL[2][4];
            uint32_t aoff = st + baseA + ks * 32;
            uint32_t boff = st + baseB + ks * 32;
            #pragma unroll
            for (int mt = 0; mt < 4; mt++)
                ldsm4(A[mt], aoff + 0*TILE_B + mt * 1280);
            #pragma unroll
            for (int p = 0; p < 2; p++)
                ldsm4(BB[p], boff + 2*TILE_B + p * 1280);
            #pragma unroll
            for (int mt = 0; mt < 4; mt++)
                #pragma unroll
                for (int nt = 0; nt < 4; nt++)
                    mma_bf16(acc[mt][nt], A[mt],
                             BB[nt>>1][(nt&1)*2], BB[nt>>1][(nt&1)*2+1]);
            #pragma unroll
            for (int p = 0; p < 2; p++)
                ldsm4(BL[p], boff + 3*TILE_B + p * 1280);
            #pragma unroll
            for (int mt = 0; mt < 4; mt++)
                #pragma unroll
                for (int nt = 0; nt < 4; nt++)
                    mma_bf16(acc[mt][nt], A[mt],
                             BL[nt>>1][(nt&1)*2], BL[nt>>1][(nt&1)*2+1]);
            #pragma unroll
            for (int mt = 0; mt < 4; mt++)
                ldsm4(A[mt], aoff + 1*TILE_B + mt * 1280);
            #pragma unroll
            for (int mt = 0; mt < 4; mt++)
                #pragma unroll
                for (int nt = 0; nt < 4; nt++)
                    mma_bf16(acc[mt][nt], A[mt],
                             BB[nt>>1][(nt&1)*2], BB[nt>>1][(nt&1)*2+1]);
        }
        __syncthreads();
    }

    int rb = m0 + m_warp + (lane >> 2);
    int cb = n0 + n_warp + (lane & 3) * 2;
    #pragma unroll
    for (int mt = 0; mt < 4; mt++) {
        #pragma unroll
        for (int nt = 0; nt < 4; nt++) {
            int r = rb + mt * 16;
            int c = cb + nt * 8;
            float2 bv = *(const float2*)(bias + c);
            float2 o0 = make_float2(acc[mt][nt][0] + bv.x, acc[mt][nt][1] + bv.y);
            float2 o1 = make_float2(acc[mt][nt][2] + bv.x, acc[mt][nt][3] + bv.y);
            *(float2*)(C + (size_t)r * DIMN + c)       = o0;
            *(float2*)(C + (size_t)(r + 8) * DIMN + c) = o1;
        }
    }
    #undef ISSUE
}

// ---------------- FA2 tensor-core attention ---------------------------------
// CTA: 64 q rows x one (b,h); 4 warps x 16 rows. s-tiles of 64.
// smem: 2 stages x [KHI|KLO|VHI|VLO], each tile 64x64 bf16, row stride 144B.
#define AT_TILE  9216
#define AT_STAGE 36864
#define ATT_SMEM 73728

__device__ __forceinline__ void load_tile64(uint32_t dst,
                                            const __nv_bfloat16* src, int tid) {
    #pragma unroll
    for (int c = 0; c < 4; c++) {
        int chunk = c * 128 + tid;
        int r = chunk >> 3, sg = chunk & 7;
        cp16(dst + r * 144 + sg * 16, src + (size_t)r * DIMN + sg * 8);
    }
}

__global__ __launch_bounds__(128, 3)
void attn_tc_kernel(const __nv_bfloat16* __restrict__ qhi_g,
                    const __nv_bfloat16* __restrict__ qlo_g,
                    const __nv_bfloat16* __restrict__ khi_g,
                    const __nv_bfloat16* __restrict__ klo_g,
                    const __nv_bfloat16* __restrict__ vhi_g,
                    const __nv_bfloat16* __restrict__ vlo_g,
                    float* __restrict__ O) {
    extern __shared__ char smem[];
    uint32_t sb = smem_u32(smem);
    int tid = threadIdx.x, wid = tid >> 5, lane = tid & 31;
    int qt = gridDim.x - 1 - blockIdx.x;      // heavy blocks first
    int h = blockIdx.y, b = blockIdx.z;
    int q0 = qt * 64;
    int q0w = q0 + wid * 16;

    size_t hoff = (size_t)h * HD;
    size_t rowbase = (size_t)(b * T_) * DIMN + hoff;
    const __nv_bfloat16* qh = qhi_g + rowbase + (size_t)q0 * DIMN;
    const __nv_bfloat16* ql = qlo_g + rowbase + (size_t)q0 * DIMN;
    const __nv_bfloat16* kh = khi_g + rowbase;
    const __nv_bfloat16* kl = klo_g + rowbase;
    const __nv_bfloat16* vh = vhi_g + rowbase;
    const __nv_bfloat16* vl = vlo_g + rowbase;

    // ---- stage Q into stage0 region, build A fragments ----
    load_tile64(sb,           qh, tid);
    load_tile64(sb + AT_TILE, ql, tid);
    CP_COMMIT();
    CP_WAIT(0);
    __syncthreads();

    uint32_t laneArow = ((lane >> 3) & 1) * 8 + (lane & 7);
    uint32_t qaddr = sb + (wid * 16 + laneArow) * 144 + (lane >> 4) * 16;
    uint32_t qfh[4][4], qfl[4][4];
    #pragma unroll
    for (int ks = 0; ks < 4; ks++) {
        ldsm4(qfh[ks], qaddr + ks * 32);
        ldsm4(qfl[ks], qaddr + AT_TILE + ks * 32);
    }
    __syncthreads();

    int ntile = q0 / 64 + 1;

    // issue first stages
    {
        uint32_t st = sb;
        load_tile64(st,             kh, tid);
        load_tile64(st + AT_TILE,   kl, tid);
        load_tile64(st + 2*AT_TILE, vh, tid);
        load_tile64(st + 3*AT_TILE, vl, tid);
        CP_COMMIT();
        if (ntile > 1) {
            uint32_t st1 = sb + AT_STAGE;
            const size_t o = (size_t)64 * DIMN;
            load_tile64(st1,             kh + o, tid);
            load_tile64(st1 + AT_TILE,   kl + o, tid);
            load_tile64(st1 + 2*AT_TILE, vh + o, tid);
            load_tile64(st1 + 3*AT_TILE, vl + o, tid);
            CP_COMMIT();
        }
    }

    float oacc[8][4];
    #pragma unroll
    for (int j = 0; j < 8; j++)
        #pragma unroll
        for (int q = 0; q < 4; q++) oacc[j][q] = 0.f;
    float m0 = -1e30f, m1 = -1e30f, l0 = 0.f, l1 = 0.f;

    uint32_t laneBrow = (lane >> 4) * 8 + (lane & 7);
    uint32_t laneBseg = ((lane >> 3) & 1) * 16;
    uint32_t laneVrow = ((lane >> 3) & 1) * 8 + (lane & 7);
    uint32_t laneVseg = (lane >> 4) * 16;

    for (int it = 0; it < ntile; it++) {
        if (it + 1 < ntile) { CP_WAIT(1); } else { CP_WAIT(0); }
        __syncthreads();
        int s0 = it * 64;
        uint32_t st = sb + (it & 1) * AT_STAGE;

        if (s0 <= q0w + 15) {
            // ---- S = Q K^T (3-product split) ----
            float sc[8][4];
            #pragma unroll
            for (int j = 0; j < 8; j++)
                #pragma unroll
                for (int q = 0; q < 4; q++) sc[j][q] = 0.f;

            #pragma unroll
            for (int p = 0; p < 4; p++) {
                uint32_t kaddr = st + (p * 16 + laneBrow) * 144 + laneBseg;
                #pragma unroll
                for (int ks = 0; ks < 4; ks++) {
                    uint32_t bh[4], bl[4];
                    ldsm4(bh, kaddr + ks * 32);
                    ldsm4(bl, kaddr + AT_TILE + ks * 32);
                    mma_bf16(sc[2*p],   qfh[ks], bh[0], bh[1]);
                    mma_bf16(sc[2*p+1], qfh[ks], bh[2], bh[3]);
                    mma_bf16(sc[2*p],   qfl[ks], bh[0], bh[1]);
                    mma_bf16(sc[2*p+1], qfl[ks], bh[2], bh[3]);
                    mma_bf16(sc[2*p],   qfh[ks], bl[0], bl[1]);
                    mma_bf16(sc[2*p+1], qfh[ks], bl[2], bl[3]);
                }
            }

            // ---- causal mask (diagonal tiles only) ----
            if (s0 + 63 > q0w) {
                int r0 = q0w + (lane >> 2), r1 = r0 + 8;
                #pragma unroll
                for (int j = 0; j < 8; j++) {
                    int c0 = s0 + j * 8 + (lane & 3) * 2;
                    if (c0     > r0) sc[j][0] = -1e30f;
                    if (c0 + 1 > r0) sc[j][1] = -1e30f;
                    if (c0     > r1) sc[j][2] = -1e30f;
                    if (c0 + 1 > r1) sc[j][3] = -1e30f;
                }
            }

            // ---- online softmax ----
            float mt0 = -1e30f, mt1 = -1e30f;
            #pragma unroll
            for (int j = 0; j < 8; j++) {
                mt0 = fmaxf(mt0, fmaxf(sc[j][0], sc[j][1]));
                mt1 = fmaxf(mt1, fmaxf(sc[j][2], sc[j][3]));
            }
            mt0 = fmaxf(mt0, __shfl_xor_sync(0xffffffffu, mt0, 1));
            mt0 = fmaxf(mt0, __shfl_xor_sync(0xffffffffu, mt0, 2));
            mt1 = fmaxf(mt1, __shfl_xor_sync(0xffffffffu, mt1, 1));
            mt1 = fmaxf(mt1, __shfl_xor_sync(0xffffffffu, mt1, 2));
            float mn0 = fmaxf(m0, mt0), mn1 = fmaxf(m1, mt1);
            float cr0 = __expf(m0 - mn0), cr1 = __expf(m1 - mn1);
            m0 = mn0; m1 = mn1;

            uint32_t phi[16], plo[16];
            float ps0 = 0.f, ps1 = 0.f;
            #pragma unroll
            for (int j = 0; j < 8; j++) {
                float p0 = __expf(sc[j][0] - mn0);
                float p1 = __expf(sc[j][1] - mn0);
                float p2 = __expf(sc[j][2] - mn1);
                float p3 = __expf(sc[j][3] - mn1);
                ps0 += p0 + p1;
                ps1 += p2 + p3;
                __nv_bfloat16 h0 = __float2bfloat16(p0);
                __nv_bfloat16 h1 = __float2bfloat16(p1);
                __nv_bfloat16 h2 = __float2bfloat16(p2);
                __nv_bfloat16 h3 = __float2bfloat16(p3);
                phi[2*j]   = bits2(__nv_bfloat162(h0, h1));
                phi[2*j+1] = bits2(__nv_bfloat162(h2, h3));
                plo[2*j]   = bits2(__nv_bfloat162(
                                 __float2bfloat16(p0 - __bfloat162float(h0)),
                                 __float2bfloat16(p1 - __bfloat162float(h1))));
                plo[2*j+1] = bits2(__nv_bfloat162(
                                 __float2bfloat16(p2 - __bfloat162float(h2)),
                                 __float2bfloat16(p3 - __bfloat162float(h3))));
            }
            ps0 += __shfl_xor_sync(0xffffffffu, ps0, 1);
            ps0 += __shfl_xor_sync(0xffffffffu, ps0, 2);
            ps1 += __shfl_xor_sync(0xffffffffu, ps1, 1);
            ps1 += __shfl_xor_sync(0xffffffffu, ps1, 2);
            l0 = l0 * cr0 + ps0;
            l1 = l1 * cr1 + ps1;

            #pragma unroll
            for (int j = 0; j < 8; j++) {
                oacc[j][0] *= cr0; oacc[j][1] *= cr0;
                oacc[j][2] *= cr1; oacc[j][3] *= cr1;
            }

            // ---- O += P V (3-product split), V^T via ldmatrix.trans ----
            #pragma unroll
            for (int dp = 0; dp < 4; dp++) {
                #pragma unroll
                for (int kp = 0; kp < 4; kp++) {
                    uint32_t vaddr = st + 2*AT_TILE +
                        (kp * 16 + laneVrow) * 144 + laneVseg + dp * 32;
                    uint32_t vh4[4], vl4[4];
                    ldsm4t(vh4, vaddr);
                    ldsm4t(vl4, vaddr + AT_TILE);
                    mma_bf16(oacc[2*dp],   &phi[4*kp], vh4[0], vh4[1]);
                    mma_bf16(oacc[2*dp+1], &phi[4*kp], vh4[2], vh4[3]);
                    mma_bf16(oacc[2*dp],   &plo[4*kp], vh4[0], vh4[1]);
                    mma_bf16(oacc[2*dp+1], &plo[4*kp], vh4[2], vh4[3]);
                    mma_bf16(oacc[2*dp],   &phi[4*kp], vl4[0], vl4[1]);
                    mma_bf16(oacc[2*dp+1], &phi[4*kp], vl4[2], vl4[3]);
                }
            }
        }
        __syncthreads();
        if (it + 2 < ntile) {
            uint32_t si = sb + (it & 1) * AT_STAGE;
            const size_t o = (size_t)(it + 2) * 64 * DIMN;
            load_tile64(si,             kh + o, tid);
            load_tile64(si + AT_TILE,   kl + o, tid);
            load_tile64(si + 2*AT_TILE, vh + o, tid);
            load_tile64(si + 3*AT_TILE, vl + o, tid);
            CP_COMMIT();
        }
    }

    // ---- write O (fp32) ----
    float i0 = 1.f / l0, i1 = 1.f / l1;
    size_t r0 = (size_t)(b * T_ + q0w + (lane >> 2)) * DIMN + hoff;
    size_t r1 = r0 + (size_t)8 * DIMN;
    #pragma unroll
    for (int j = 0; j < 8; j++) {
        int col = j * 8 + (lane & 3) * 2;
        *(float2*)(O + r0 + col) = make_float2(oacc[j][0] * i0, oacc[j][1] * i0);
        *(float2*)(O + r1 + col) = make_float2(oacc[j][2] * i1, oacc[j][3] * i1);
    }
}

// ---------------- launch ---------------------------------------------------
extern "C" void kernel_launch(void* const* d_in, const int* in_sizes, int n_in,
                              void* d_out, int out_size) {
    const float* query = (const float*)d_in[0];
    const float* key   = (const float*)d_in[1];
    const float* value = (const float*)d_in[2];
    const float* Wq    = (const float*)d_in[3];
    const float* bq    = (const float*)d_in[4];
    const float* Wk    = (const float*)d_in[5];
    const float* bk    = (const float*)d_in[6];
    const float* Wv    = (const float*)d_in[7];
    const float* bv    = (const float*)d_in[8];
    const float* Wo    = (const float*)d_in[9];
    const float* bo    = (const float*)d_in[10];
    float* out = (float*)d_out;

    float *qb, *kb, *vb, *ob;
    __nv_bfloat16 *ahi, *alo, *whT, *wlT;
    __nv_bfloat16 *qhi, *qlo, *khi, *klo, *vhi, *vlo;
    cudaGetSymbolAddress((void**)&qb, g_q);
    cudaGetSymbolAddress((void**)&kb, g_k);
    cudaGetSymbolAddress((void**)&vb, g_v);
    cudaGetSymbolAddress((void**)&ob, g_o);
    cudaGetSymbolAddress((void**)&ahi, g_ahi);
    cudaGetSymbolAddress((void**)&alo, g_alo);
    cudaGetSymbolAddress((void**)&whT, g_whT);
    cudaGetSymbolAddress((void**)&wlT, g_wlT);
    cudaGetSymbolAddress((void**)&qhi, g_qhi);
    cudaGetSymbolAddress((void**)&qlo, g_qlo);
    cudaGetSymbolAddress((void**)&khi, g_khi);
    cudaGetSymbolAddress((void**)&klo, g_klo);
    cudaGetSymbolAddress((void**)&vhi, g_vhi);
    cudaGetSymbolAddress((void**)&vlo, g_vlo);

    static bool attr_set = false;
    if (!attr_set) {
        cudaFuncSetAttribute(gemm_tc_kernel,
                             cudaFuncAttributeMaxDynamicSharedMemorySize, GEMM_SMEM);
        cudaFuncSetAttribute(attn_tc_kernel,
                             cudaFuncAttributeMaxDynamicSharedMemorySize, ATT_SMEM);
        attr_set = true;
    }

    rope_tables_kernel<<<(T_*32 + 255) / 256, 256>>>();

    dim3 wt_grid(32, 32), wt_blk(32, 8);
    dim3 ggrid(DIMN / 128, MROWS / 128);
    int n4 = MROWS * DIMN / 4;
    int cvt_blocks = (n4 + 255) / 256;

    // Q projection
    convert_wt_kernel<<<wt_grid, wt_blk>>>(Wq, whT, wlT);
    convert_act_kernel<<<cvt_blocks, 256>>>(query, ahi, alo, n4);
    gemm_tc_kernel<<<ggrid, 256, GEMM_SMEM>>>(ahi, alo, whT, wlT, bq, qb);
    // K projection
    convert_wt_kernel<<<wt_grid, wt_blk>>>(Wk, whT, wlT);
    convert_act_kernel<<<cvt_blocks, 256>>>(key, ahi, alo, n4);
    gemm_tc_kernel<<<ggrid, 256, GEMM_SMEM>>>(ahi, alo, whT, wlT, bk, kb);
    // V projection
    convert_wt_kernel<<<wt_grid, wt_blk>>>(Wv, whT, wlT);
    convert_act_kernel<<<cvt_blocks, 256>>>(value, ahi, alo, n4);
    gemm_tc_kernel<<<ggrid, 256, GEMM_SMEM>>>(ahi, alo, whT, wlT, bv, vb);

    // RoPE + split to bf16 (q scaled by 1/8), V plain split
    int npairs = MROWS * 512;
    rope_split_kernel<<<(npairs + 255) / 256, 256>>>(qb, qhi, qlo, 0.125f);
    rope_split_kernel<<<(npairs + 255) / 256, 256>>>(kb, khi, klo, 1.0f);
    convert_act_kernel<<<cvt_blocks, 256>>>(vb, vhi, vlo, n4);

    // tensor-core flash attention
    dim3 agrid(T_ / 64, H_, B_);
    attn_tc_kernel<<<agrid, 128, ATT_SMEM>>>(qhi, qlo, khi, klo, vhi, vlo, ob);

    // output projection
    convert_wt_kernel<<<wt_grid, wt_blk>>>(Wo, whT, wlT);
    convert_act_kernel<<<cvt_blocks, 256>>>(ob, ahi, alo, n4);
    gemm_tc_kernel<<<ggrid, 256, GEMM_SMEM>>>(ahi, alo, whT, wlT, bo, out);
}

// round 6
// speedup vs baseline: 4.6183x; 1.0161x over previous
#include <cuda_runtime.h>
#include <cuda_bf16.h>
#include <math.h>
#include <stdint.h>

#define B_   4
#define T_   2048
#define DIMN 1024
#define H_   16
#define HD   64
#define MROWS (B_*T_)          // 8192

// ---------------- smem / mma helpers ----------------------------------------
__device__ __forceinline__ uint32_t smem_u32(const void* p) {
    uint32_t a;
    asm("{ .reg .u64 t; cvta.to.shared.u64 t, %1; cvt.u32.u64 %0, t; }"
        : "=r"(a) : "l"(p));
    return a;
}
__device__ __forceinline__ void cp16(uint32_t dst, const void* src) {
    asm volatile("cp.async.cg.shared.global [%0], [%1], 16;"
                 :: "r"(dst), "l"(src) : "memory");
}
#define CP_COMMIT() asm volatile("cp.async.commit_group;" ::: "memory")
#define CP_WAIT(n)  asm volatile("cp.async.wait_group %0;" :: "n"(n) : "memory")

__device__ __forceinline__ void ldsm4(uint32_t* r, uint32_t addr) {
    asm volatile("ldmatrix.sync.aligned.m8n8.x4.shared.b16 {%0,%1,%2,%3}, [%4];"
                 : "=r"(r[0]), "=r"(r[1]), "=r"(r[2]), "=r"(r[3]) : "r"(addr));
}
__device__ __forceinline__ void ldsm4t(uint32_t* r, uint32_t addr) {
    asm volatile("ldmatrix.sync.aligned.m8n8.x4.trans.shared.b16 {%0,%1,%2,%3}, [%4];"
                 : "=r"(r[0]), "=r"(r[1]), "=r"(r[2]), "=r"(r[3]) : "r"(addr));
}
__device__ __forceinline__ void mma_bf16(float* c, const uint32_t* a,
                                         uint32_t b0, uint32_t b1) {
    asm volatile(
        "mma.sync.aligned.m16n8k16.row.col.f32.bf16.bf16.f32 "
        "{%0,%1,%2,%3}, {%4,%5,%6,%7}, {%8,%9}, {%0,%1,%2,%3};"
        : "+f"(c[0]), "+f"(c[1]), "+f"(c[2]), "+f"(c[3])
        : "r"(a[0]), "r"(a[1]), "r"(a[2]), "r"(a[3]), "r"(b0), "r"(b1));
}
__device__ __forceinline__ uint32_t bits2(__nv_bfloat162 v) {
    return *reinterpret_cast<uint32_t*>(&v);
}
__device__ __forceinline__ void split_store(__nv_bfloat16* hi, __nv_bfloat16* lo,
                                            size_t off, float x, float y) {
    __nv_bfloat16 hx = __float2bfloat16(x);
    __nv_bfloat16 hy = __float2bfloat16(y);
    *(__nv_bfloat162*)(hi + off) = __nv_bfloat162(hx, hy);
    *(__nv_bfloat162*)(lo + off) =
        __nv_bfloat162(__float2bfloat16(x - __bfloat162float(hx)),
                       __float2bfloat16(y - __bfloat162float(hy)));
}

// ---------------- scratch (device globals) ----------------------------------
__device__ float g_cos[T_*32];
__device__ float g_sin[T_*32];
__device__ __nv_bfloat16 g_ahi[MROWS*DIMN];
__device__ __nv_bfloat16 g_alo[MROWS*DIMN];
__device__ __nv_bfloat16 g_whT[DIMN*DIMN];
__device__ __nv_bfloat16 g_wlT[DIMN*DIMN];
__device__ __nv_bfloat16 g_qhi[MROWS*DIMN];
__device__ __nv_bfloat16 g_qlo[MROWS*DIMN];
__device__ __nv_bfloat16 g_khi[MROWS*DIMN];
__device__ __nv_bfloat16 g_klo[MROWS*DIMN];
__device__ __nv_bfloat16 g_vhi[MROWS*DIMN];
__device__ __nv_bfloat16 g_vlo[MROWS*DIMN];

// ---------------- RoPE tables -----------------------------------------------
__global__ void rope_tables_kernel() {
    int idx = blockIdx.x * blockDim.x + threadIdx.x;
    if (idx >= T_*32) return;
    int t = idx >> 5;
    int j = idx & 31;
    double inv = pow(10000.0, -(double)(2*j) / 64.0);
    float invf = (float)inv;
    float freq = (float)t * invf;
    g_cos[idx] = (float)cos((double)freq);
    g_sin[idx] = (float)sin((double)freq);
}

// ---------------- fp32 -> bf16 hi/lo split -----------------------------------
__global__ void convert_act_kernel(const float* __restrict__ x,
                                   __nv_bfloat16* __restrict__ hi,
                                   __nv_bfloat16* __restrict__ lo, int n4) {
    int i = blockIdx.x * blockDim.x + threadIdx.x;
    if (i >= n4) return;
    float4 v = ((const float4*)x)[i];
    __nv_bfloat16 h0 = __float2bfloat16(v.x);
    __nv_bfloat16 h1 = __float2bfloat16(v.y);
    __nv_bfloat16 h2 = __float2bfloat16(v.z);
    __nv_bfloat16 h3 = __float2bfloat16(v.w);
    __nv_bfloat162* hp = (__nv_bfloat162*)hi;
    __nv_bfloat162* lp = (__nv_bfloat162*)lo;
    hp[2*i]   = __nv_bfloat162(h0, h1);
    hp[2*i+1] = __nv_bfloat162(h2, h3);
    lp[2*i]   = __nv_bfloat162(__float2bfloat16(v.x - __bfloat162float(h0)),
                               __float2bfloat16(v.y - __bfloat162float(h1)));
    lp[2*i+1] = __nv_bfloat162(__float2bfloat16(v.z - __bfloat162float(h2)),
                               __float2bfloat16(v.w - __bfloat162float(h3)));
}

// ---------------- fp32 W[k][n] -> bf16 hi/lo transposed [n][k] --------------
__global__ void convert_wt_kernel(const float* __restrict__ W,
                                  __nv_bfloat16* __restrict__ hiT,
                                  __nv_bfloat16* __restrict__ loT) {
    __shared__ float t[32][33];
    int tx = threadIdx.x, ty = threadIdx.y;   // 32 x 8
    int n0 = blockIdx.x * 32, k0 = blockIdx.y * 32;
    #pragma unroll
    for (int i = 0; i < 32; i += 8)
        t[ty + i][tx] = W[(size_t)(k0 + ty + i) * DIMN + n0 + tx];
    __syncthreads();
    #pragma unroll
    for (int i = 0; i < 32; i += 8) {
        float x = t[tx][ty + i];
        __nv_bfloat16 h = __float2bfloat16(x);
        size_t o = (size_t)(n0 + ty + i) * DIMN + k0 + tx;
        hiT[o] = h;
        loT[o] = __float2bfloat16(x - __bfloat162float(h));
    }
}

// ---------------- mma.sync bf16-split GEMM with fused epilogues --------------
// EPI 0: C = fp32 (acc+bias).  EPI 1: bias -> bf16 hi/lo split.
// EPI 2: bias -> RoPE -> *scale -> bf16 hi/lo split.
#define TILE_B   10240
#define STAGE_B  40960
#define GEMM_SMEM (2*STAGE_B)

template <int EPI>
__global__ __launch_bounds__(256, 2)
void gemm_tc_kernel(const __nv_bfloat16* __restrict__ a_hi,
                    const __nv_bfloat16* __restrict__ a_lo,
                    const __nv_bfloat16* __restrict__ w_hiT,
                    const __nv_bfloat16* __restrict__ w_loT,
                    const float* __restrict__ bias,
                    float* __restrict__ Cf,
                    __nv_bfloat16* __restrict__ Chi,
                    __nv_bfloat16* __restrict__ Clo,
                    float scale) {
    extern __shared__ char smem[];
    uint32_t sb = smem_u32(smem);
    int tid = threadIdx.x, wid = tid >> 5, lane = tid & 31;
    int m0 = blockIdx.y * 128, n0 = blockIdx.x * 128;

    const __nv_bfloat16* srcA_hi = a_hi  + (size_t)m0 * DIMN;
    const __nv_bfloat16* srcA_lo = a_lo  + (size_t)m0 * DIMN;
    const __nv_bfloat16* srcW_hi = w_hiT + (size_t)n0 * DIMN;
    const __nv_bfloat16* srcW_lo = w_loT + (size_t)n0 * DIMN;

    int r0 = tid >> 2, sg = tid & 3;
    int r1 = r0 + 64;
    uint32_t so0 = (uint32_t)r0 * 80 + sg * 16;
    uint32_t so1 = (uint32_t)r1 * 80 + sg * 16;
    size_t go0 = (size_t)r0 * DIMN + sg * 8;
    size_t go1 = (size_t)r1 * DIMN + sg * 8;

    #define ISSUE(stage, k0)  do {                                            \
        uint32_t _sbs = sb + (stage) * STAGE_B;                               \
        cp16(_sbs + 0*TILE_B + so0, srcA_hi + (k0) + go0);                    \
        cp16(_sbs + 0*TILE_B + so1, srcA_hi + (k0) + go1);                    \
        cp16(_sbs + 1*TILE_B + so0, srcA_lo + (k0) + go0);                    \
        cp16(_sbs + 1*TILE_B + so1, srcA_lo + (k0) + go1);                    \
        cp16(_sbs + 2*TILE_B + so0, srcW_hi + (k0) + go0);                    \
        cp16(_sbs + 2*TILE_B + so1, srcW_hi + (k0) + go1);                    \
        cp16(_sbs + 3*TILE_B + so0, srcW_lo + (k0) + go0);                    \
        cp16(_sbs + 3*TILE_B + so1, srcW_lo + (k0) + go1);                    \
    } while (0)

    int m_warp = (wid & 1) * 64;
    int n_warp = (wid >> 1) * 32;
    uint32_t laneA_row = ((lane >> 3) & 1) * 8 + (lane & 7);
    uint32_t laneA_col = (lane >> 4) * 8;
    uint32_t laneB_row = (lane >> 4) * 8 + (lane & 7);
    uint32_t laneB_col = ((lane >> 3) & 1) * 8;
    uint32_t baseA = (uint32_t)(m_warp + laneA_row) * 80 + laneA_col * 2;
    uint32_t baseB = (uint32_t)(n_warp + laneB_row) * 80 + laneB_col * 2;

    float acc[4][4][4];
    #pragma unroll
    for (int i = 0; i < 4; i++)
        #pragma unroll
        for (int j = 0; j < 4; j++)
            #pragma unroll
            for (int q = 0; q < 4; q++) acc[i][j][q] = 0.f;

    ISSUE(0, 0);
    CP_COMMIT();

    for (int kc = 0; kc < 32; kc++) {
        if (kc < 31) {
            ISSUE((kc + 1) & 1, (kc + 1) * 32);
            CP_COMMIT();
            CP_WAIT(1);
        } else {
            CP_WAIT(0);
        }
        __syncthreads();

        uint32_t st = sb + (kc & 1) * STAGE_B;
        #pragma unroll
        for (int ks = 0; ks < 2; ks++) {
            uint32_t A[4][4], BB[2][4], BL[2][4];
            uint32_t aoff = st + baseA + ks * 32;
            uint32_t boff = st + baseB + ks * 32;
            // load A_hi + ALL B fragments up front -> 32 uninterrupted mmas
            #pragma unroll
            for (int mt = 0; mt < 4; mt++)
                ldsm4(A[mt], aoff + 0*TILE_B + mt * 1280);
            #pragma unroll
            for (int p = 0; p < 2; p++)
                ldsm4(BB[p], boff + 2*TILE_B + p * 1280);
            #pragma unroll
            for (int p = 0; p < 2; p++)
                ldsm4(BL[p], boff + 3*TILE_B + p * 1280);
            #pragma unroll
            for (int mt = 0; mt < 4; mt++)
                #pragma unroll
                for (int nt = 0; nt < 4; nt++)
                    mma_bf16(acc[mt][nt], A[mt],
                             BB[nt>>1][(nt&1)*2], BB[nt>>1][(nt&1)*2+1]);
            #pragma unroll
            for (int mt = 0; mt < 4; mt++)
                #pragma unroll
                for (int nt = 0; nt < 4; nt++)
                    mma_bf16(acc[mt][nt], A[mt],
                             BL[nt>>1][(nt&1)*2], BL[nt>>1][(nt&1)*2+1]);
            #pragma unroll
            for (int mt = 0; mt < 4; mt++)
                ldsm4(A[mt], aoff + 1*TILE_B + mt * 1280);
            #pragma unroll
            for (int mt = 0; mt < 4; mt++)
                #pragma unroll
                for (int nt = 0; nt < 4; nt++)
                    mma_bf16(acc[mt][nt], A[mt],
                             BB[nt>>1][(nt&1)*2], BB[nt>>1][(nt&1)*2+1]);
        }
        __syncthreads();
    }

    int rb = m0 + m_warp + (lane >> 2);
    int cb = n0 + n_warp + (lane & 3) * 2;
    #pragma unroll
    for (int mt = 0; mt < 4; mt++) {
        #pragma unroll
        for (int nt = 0; nt < 4; nt++) {
            int r = rb + mt * 16;
            int c = cb + nt * 8;
            float2 bv = *(const float2*)(bias + c);
            float x0 = acc[mt][nt][0] + bv.x, y0 = acc[mt][nt][1] + bv.y;
            float x1 = acc[mt][nt][2] + bv.x, y1 = acc[mt][nt][3] + bv.y;
            if (EPI == 0) {
                *(float2*)(Cf + (size_t)r * DIMN + c)       = make_float2(x0, y0);
                *(float2*)(Cf + (size_t)(r + 8) * DIMN + c) = make_float2(x1, y1);
            } else if (EPI == 1) {
                split_store(Chi, Clo, (size_t)r * DIMN + c, x0, y0);
                split_store(Chi, Clo, (size_t)(r + 8) * DIMN + c, x1, y1);
            } else {
                int j = (c & 63) >> 1;
                int t0 = r & (T_ - 1), t1 = (r + 8) & (T_ - 1);
                float c0 = g_cos[t0*32 + j], s0 = g_sin[t0*32 + j];
                float c1 = g_cos[t1*32 + j], s1 = g_sin[t1*32 + j];
                float rx0 = (x0 * c0 - y0 * s0) * scale;
                float ry0 = (x0 * s0 + y0 * c0) * scale;
                float rx1 = (x1 * c1 - y1 * s1) * scale;
                float ry1 = (x1 * s1 + y1 * c1) * scale;
                split_store(Chi, Clo, (size_t)r * DIMN + c, rx0, ry0);
                split_store(Chi, Clo, (size_t)(r + 8) * DIMN + c, rx1, ry1);
            }
        }
    }
    #undef ISSUE
}

// ---------------- FA2 tensor-core attention ---------------------------------
// CTA: 64 q rows x one (b,h); 4 warps x 16 rows. s-tiles of 64.
// Output written as bf16 hi/lo split (input of O projection).
#define AT_TILE  9216
#define AT_STAGE 36864
#define ATT_SMEM 73728

__device__ __forceinline__ void load_tile64(uint32_t dst,
                                            const __nv_bfloat16* src, int tid) {
    #pragma unroll
    for (int c = 0; c < 4; c++) {
        int chunk = c * 128 + tid;
        int r = chunk >> 3, sg = chunk & 7;
        cp16(dst + r * 144 + sg * 16, src + (size_t)r * DIMN + sg * 8);
    }
}

__global__ __launch_bounds__(128, 3)
void attn_tc_kernel(const __nv_bfloat16* __restrict__ qhi_g,
                    const __nv_bfloat16* __restrict__ qlo_g,
                    const __nv_bfloat16* __restrict__ khi_g,
                    const __nv_bfloat16* __restrict__ klo_g,
                    const __nv_bfloat16* __restrict__ vhi_g,
                    const __nv_bfloat16* __restrict__ vlo_g,
                    __nv_bfloat16* __restrict__ Ohi,
                    __nv_bfloat16* __restrict__ Olo) {
    extern __shared__ char smem[];
    uint32_t sb = smem_u32(smem);
    int tid = threadIdx.x, wid = tid >> 5, lane = tid & 31;
    int qt = gridDim.x - 1 - blockIdx.x;      // heavy blocks first
    int h = blockIdx.y, b = blockIdx.z;
    int q0 = qt * 64;
    int q0w = q0 + wid * 16;

    size_t hoff = (size_t)h * HD;
    size_t rowbase = (size_t)(b * T_) * DIMN + hoff;
    const __nv_bfloat16* qh = qhi_g + rowbase + (size_t)q0 * DIMN;
    const __nv_bfloat16* ql = qlo_g + rowbase + (size_t)q0 * DIMN;
    const __nv_bfloat16* kh = khi_g + rowbase;
    const __nv_bfloat16* kl = klo_g + rowbase;
    const __nv_bfloat16* vh = vhi_g + rowbase;
    const __nv_bfloat16* vl = vlo_g + rowbase;

    load_tile64(sb,           qh, tid);
    load_tile64(sb + AT_TILE, ql, tid);
    CP_COMMIT();
    CP_WAIT(0);
    __syncthreads();

    uint32_t laneArow = ((lane >> 3) & 1) * 8 + (lane & 7);
    uint32_t qaddr = sb + (wid * 16 + laneArow) * 144 + (lane >> 4) * 16;
    uint32_t qfh[4][4], qfl[4][4];
    #pragma unroll
    for (int ks = 0; ks < 4; ks++) {
        ldsm4(qfh[ks], qaddr + ks * 32);
        ldsm4(qfl[ks], qaddr + AT_TILE + ks * 32);
    }
    __syncthreads();

    int ntile = q0 / 64 + 1;

    {
        uint32_t st = sb;
        load_tile64(st,             kh, tid);
        load_tile64(st + AT_TILE,   kl, tid);
        load_tile64(st + 2*AT_TILE, vh, tid);
        load_tile64(st + 3*AT_TILE, vl, tid);
        CP_COMMIT();
        if (ntile > 1) {
            uint32_t st1 = sb + AT_STAGE;
            const size_t o = (size_t)64 * DIMN;
            load_tile64(st1,             kh + o, tid);
            load_tile64(st1 + AT_TILE,   kl + o, tid);
            load_tile64(st1 + 2*AT_TILE, vh + o, tid);
            load_tile64(st1 + 3*AT_TILE, vl + o, tid);
            CP_COMMIT();
        }
    }

    float oacc[8][4];
    #pragma unroll
    for (int j = 0; j < 8; j++)
        #pragma unroll
        for (int q = 0; q < 4; q++) oacc[j][q] = 0.f;
    float m0 = -1e30f, m1 = -1e30f, l0 = 0.f, l1 = 0.f;

    uint32_t laneBrow = (lane >> 4) * 8 + (lane & 7);
    uint32_t laneBseg = ((lane >> 3) & 1) * 16;
    uint32_t laneVrow = ((lane >> 3) & 1) * 8 + (lane & 7);
    uint32_t laneVseg = (lane >> 4) * 16;

    for (int it = 0; it < ntile; it++) {
        if (it + 1 < ntile) { CP_WAIT(1); } else { CP_WAIT(0); }
        __syncthreads();
        int s0 = it * 64;
        uint32_t st = sb + (it & 1) * AT_STAGE;

        if (s0 <= q0w + 15) {
            float sc[8][4];
            #pragma unroll
            for (int j = 0; j < 8; j++)
                #pragma unroll
                for (int q = 0; q < 4; q++) sc[j][q] = 0.f;

            #pragma unroll
            for (int p = 0; p < 4; p++) {
                uint32_t kaddr = st + (p * 16 + laneBrow) * 144 + laneBseg;
                #pragma unroll
                for (int ks = 0; ks < 4; ks++) {
                    uint32_t bh[4], bl[4];
                    ldsm4(bh, kaddr + ks * 32);
                    ldsm4(bl, kaddr + AT_TILE + ks * 32);
                    mma_bf16(sc[2*p],   qfh[ks], bh[0], bh[1]);
                    mma_bf16(sc[2*p+1], qfh[ks], bh[2], bh[3]);
                    mma_bf16(sc[2*p],   qfl[ks], bh[0], bh[1]);
                    mma_bf16(sc[2*p+1], qfl[ks], bh[2], bh[3]);
                    mma_bf16(sc[2*p],   qfh[ks], bl[0], bl[1]);
                    mma_bf16(sc[2*p+1], qfh[ks], bl[2], bl[3]);
                }
            }

            if (s0 + 63 > q0w) {
                int r0 = q0w + (lane >> 2), r1 = r0 + 8;
                #pragma unroll
                for (int j = 0; j < 8; j++) {
                    int c0 = s0 + j * 8 + (lane & 3) * 2;
                    if (c0     > r0) sc[j][0] = -1e30f;
                    if (c0 + 1 > r0) sc[j][1] = -1e30f;
                    if (c0     > r1) sc[j][2] = -1e30f;
                    if (c0 + 1 > r1) sc[j][3] = -1e30f;
                }
            }

            float mt0 = -1e30f, mt1 = -1e30f;
            #pragma unroll
            for (int j = 0; j < 8; j++) {
                mt0 = fmaxf(mt0, fmaxf(sc[j][0], sc[j][1]));
                mt1 = fmaxf(mt1, fmaxf(sc[j][2], sc[j][3]));
            }
            mt0 = fmaxf(mt0, __shfl_xor_sync(0xffffffffu, mt0, 1));
            mt0 = fmaxf(mt0, __shfl_xor_sync(0xffffffffu, mt0, 2));
            mt1 = fmaxf(mt1, __shfl_xor_sync(0xffffffffu, mt1, 1));
            mt1 = fmaxf(mt1, __shfl_xor_sync(0xffffffffu, mt1, 2));
            float mn0 = fmaxf(m0, mt0), mn1 = fmaxf(m1, mt1);
            float cr0 = __expf(m0 - mn0), cr1 = __expf(m1 - mn1);
            m0 = mn0; m1 = mn1;

            uint32_t phi[16], plo[16];
            float ps0 = 0.f, ps1 = 0.f;
            #pragma unroll
            for (int j = 0; j < 8; j++) {
                float p0 = __expf(sc[j][0] - mn0);
                float p1 = __expf(sc[j][1] - mn0);
                float p2 = __expf(sc[j][2] - mn1);
                float p3 = __expf(sc[j][3] - mn1);
                ps0 += p0 + p1;
                ps1 += p2 + p3;
                __nv_bfloat16 h0 = __float2bfloat16(p0);
                __nv_bfloat16 h1 = __float2bfloat16(p1);
                __nv_bfloat16 h2 = __float2bfloat16(p2);
                __nv_bfloat16 h3 = __float2bfloat16(p3);
                phi[2*j]   = bits2(__nv_bfloat162(h0, h1));
                phi[2*j+1] = bits2(__nv_bfloat162(h2, h3));
                plo[2*j]   = bits2(__nv_bfloat162(
                                 __float2bfloat16(p0 - __bfloat162float(h0)),
                                 __float2bfloat16(p1 - __bfloat162float(h1))));
                plo[2*j+1] = bits2(__nv_bfloat162(
                                 __float2bfloat16(p2 - __bfloat162float(h2)),
                                 __float2bfloat16(p3 - __bfloat162float(h3))));
            }
            ps0 += __shfl_xor_sync(0xffffffffu, ps0, 1);
            ps0 += __shfl_xor_sync(0xffffffffu, ps0, 2);
            ps1 += __shfl_xor_sync(0xffffffffu, ps1, 1);
            ps1 += __shfl_xor_sync(0xffffffffu, ps1, 2);
            l0 = l0 * cr0 + ps0;
            l1 = l1 * cr1 + ps1;

            #pragma unroll
            for (int j = 0; j < 8; j++) {
                oacc[j][0] *= cr0; oacc[j][1] *= cr0;
                oacc[j][2] *= cr1; oacc[j][3] *= cr1;
            }

            #pragma unroll
            for (int dp = 0; dp < 4; dp++) {
                #pragma unroll
                for (int kp = 0; kp < 4; kp++) {
                    uint32_t vaddr = st + 2*AT_TILE +
                        (kp * 16 + laneVrow) * 144 + laneVseg + dp * 32;
                    uint32_t vh4[4], vl4[4];
                    ldsm4t(vh4, vaddr);
                    ldsm4t(vl4, vaddr + AT_TILE);
                    mma_bf16(oacc[2*dp],   &phi[4*kp], vh4[0], vh4[1]);
                    mma_bf16(oacc[2*dp+1], &phi[4*kp], vh4[2], vh4[3]);
                    mma_bf16(oacc[2*dp],   &plo[4*kp], vh4[0], vh4[1]);
                    mma_bf16(oacc[2*dp+1], &plo[4*kp], vh4[2], vh4[3]);
                    mma_bf16(oacc[2*dp],   &phi[4*kp], vl4[0], vl4[1]);
                    mma_bf16(oacc[2*dp+1], &phi[4*kp], vl4[2], vl4[3]);
                }
            }
        }
        __syncthreads();
        if (it + 2 < ntile) {
            uint32_t si = sb + (it & 1) * AT_STAGE;
            const size_t o = (size_t)(it + 2) * 64 * DIMN;
            load_tile64(si,             kh + o, tid);
            load_tile64(si + AT_TILE,   kl + o, tid);
            load_tile64(si + 2*AT_TILE, vh + o, tid);
            load_tile64(si + 3*AT_TILE, vl + o, tid);
            CP_COMMIT();
        }
    }

    // ---- write O as bf16 hi/lo split (feeds O-projection GEMM) ----
    float i0 = 1.f / l0, i1 = 1.f / l1;
    size_t r0 = (size_t)(b * T_ + q0w + (lane >> 2)) * DIMN + hoff;
    size_t r1 = r0 + (size_t)8 * DIMN;
    #pragma unroll
    for (int j = 0; j < 8; j++) {
        int col = j * 8 + (lane & 3) * 2;
        split_store(Ohi, Olo, r0 + col, oacc[j][0] * i0, oacc[j][1] * i0);
        split_store(Ohi, Olo, r1 + col, oacc[j][2] * i1, oacc[j][3] * i1);
    }
}

// ---------------- launch ---------------------------------------------------
extern "C" void kernel_launch(void* const* d_in, const int* in_sizes, int n_in,
                              void* d_out, int out_size) {
    const float* query = (const float*)d_in[0];
    const float* key   = (const float*)d_in[1];
    const float* value = (const float*)d_in[2];
    const float* Wq    = (const float*)d_in[3];
    const float* bq    = (const float*)d_in[4];
    const float* Wk    = (const float*)d_in[5];
    const float* bk    = (const float*)d_in[6];
    const float* Wv    = (const float*)d_in[7];
    const float* bv    = (const float*)d_in[8];
    const float* Wo    = (const float*)d_in[9];
    const float* bo    = (const float*)d_in[10];
    float* out = (float*)d_out;

    __nv_bfloat16 *ahi, *alo, *whT, *wlT;
    __nv_bfloat16 *qhi, *qlo, *khi, *klo, *vhi, *vlo;
    cudaGetSymbolAddress((void**)&ahi, g_ahi);
    cudaGetSymbolAddress((void**)&alo, g_alo);
    cudaGetSymbolAddress((void**)&whT, g_whT);
    cudaGetSymbolAddress((void**)&wlT, g_wlT);
    cudaGetSymbolAddress((void**)&qhi, g_qhi);
    cudaGetSymbolAddress((void**)&qlo, g_qlo);
    cudaGetSymbolAddress((void**)&khi, g_khi);
    cudaGetSymbolAddress((void**)&klo, g_klo);
    cudaGetSymbolAddress((void**)&vhi, g_vhi);
    cudaGetSymbolAddress((void**)&vlo, g_vlo);

    static bool attr_set = false;
    if (!attr_set) {
        cudaFuncSetAttribute(gemm_tc_kernel<0>,
                             cudaFuncAttributeMaxDynamicSharedMemorySize, GEMM_SMEM);
        cudaFuncSetAttribute(gemm_tc_kernel<1>,
                             cudaFuncAttributeMaxDynamicSharedMemorySize, GEMM_SMEM);
        cudaFuncSetAttribute(gemm_tc_kernel<2>,
                             cudaFuncAttributeMaxDynamicSharedMemorySize, GEMM_SMEM);
        cudaFuncSetAttribute(attn_tc_kernel,
                             cudaFuncAttributeMaxDynamicSharedMemorySize, ATT_SMEM);
        attr_set = true;
    }

    rope_tables_kernel<<<(T_*32 + 255) / 256, 256>>>();

    dim3 wt_grid(32, 32), wt_blk(32, 8);
    dim3 ggrid(DIMN / 128, MROWS / 128);
    int n4 = MROWS * DIMN / 4;
    int cvt_blocks = (n4 + 255) / 256;

    // Q projection (fused bias + RoPE + 1/8 scale + split)
    convert_wt_kernel<<<wt_grid, wt_blk>>>(Wq, whT, wlT);
    convert_act_kernel<<<cvt_blocks, 256>>>(query, ahi, alo, n4);
    gemm_tc_kernel<2><<<ggrid, 256, GEMM_SMEM>>>(ahi, alo, whT, wlT, bq,
                                                 nullptr, qhi, qlo, 0.125f);
    // K projection (fused bias + RoPE + split)
    convert_wt_kernel<<<wt_grid, wt_blk>>>(Wk, whT, wlT);
    convert_act_kernel<<<cvt_blocks, 256>>>(key, ahi, alo, n4);
    gemm_tc_kernel<2><<<ggrid, 256, GEMM_SMEM>>>(ahi, alo, whT, wlT, bk,
                                                 nullptr, khi, klo, 1.0f);
    // V projection (fused bias + split)
    convert_wt_kernel<<<wt_grid, wt_blk>>>(Wv, whT, wlT);
    convert_act_kernel<<<cvt_blocks, 256>>>(value, ahi, alo, n4);
    gemm_tc_kernel<1><<<ggrid, 256, GEMM_SMEM>>>(ahi, alo, whT, wlT, bv,
                                                 nullptr, vhi, vlo, 1.0f);

    // tensor-core flash attention -> bf16 hi/lo (reuses ahi/alo)
    dim3 agrid(T_ / 64, H_, B_);
    attn_tc_kernel<<<agrid, 128, ATT_SMEM>>>(qhi, qlo, khi, klo, vhi, vlo,
                                             ahi, alo);

    // output projection (fp32 out + bias)
    convert_wt_kernel<<<wt_grid, wt_blk>>>(Wo, whT, wlT);
    gemm_tc_kernel<0><<<ggrid, 256, GEMM_SMEM>>>(ahi, alo, whT, wlT, bo,
                                                 out, nullptr, nullptr, 1.0f);
}